// round 5
// baseline (speedup 1.0000x reference)
#include <cuda_runtime.h>
#include <cstdint>

// ---------------- Problem constants ----------------
#define NN 50000
#define EE 800000
#define KIN 256
#define HD 4
#define DD 64
#define OUTF (HD*DD)   // 256

// ---------------- Scratch (static device globals; no allocation) ----------------
// NOTE: these are referenced ONLY from device code. Passing a __device__ symbol
// as a host-side kernel argument yields the host shadow address (the R2-R4 bug).
__device__ float  g_hp[(size_t)NN * OUTF];     // projected features [N,256]  (~51.2MB)
__device__ float4 g_ssrc[NN];                  // per-node src logits [N,4]
__device__ float4 g_sdst[NN];                  // per-node dst logits [N,4]
__device__ int    g_deg[NN];
__device__ int    g_off[NN];
__device__ int    g_cursor[NN];
__device__ int    g_csr[EE];                   // src node ids grouped by dst
__device__ int    g_stride;                    // 1 = int32 indices, 2 = int64 (low word)

// ---------------- detect int64 vs int32 edge_index ----------------
__global__ void detect_kernel(const int* __restrict__ ei) {
    if (blockIdx.x == 0 && threadIdx.x == 0) {
        int odd_nz = 0, even_nz = 0;
        for (int i = 0; i < 512; i++) {
            if (ei[2 * i + 1] != 0) odd_nz++;
            if (ei[2 * i] != 0)     even_nz++;
        }
        g_stride = (odd_nz == 0 && even_nz > 0) ? 2 : 1;
    }
}

// ---------------- 0: zero degree ----------------
__global__ void zero_deg_kernel() {
    int i = blockIdx.x * blockDim.x + threadIdx.x;
    if (i < NN) g_deg[i] = 0;
}

// ---------------- 1: SGEMM  g_hp[M,256] = A[M,256] @ B[256,256] ----------------
#define BM 128
#define BN 128
#define BK 16
#define TM 8
#define TN 8

__global__ __launch_bounds__(256, 2)
void sgemm_kernel(const float* __restrict__ A, const float* __restrict__ B, int M) {
    __shared__ float As[BK][BM + 4];
    __shared__ float Bs[BK][BN];
    const int K = KIN;
    int tid = threadIdx.x;
    int tx = tid % 16, ty = tid / 16;
    int rowBase = blockIdx.y * BM;
    int colBase = blockIdx.x * BN;

    float acc[TM][TN];
    #pragma unroll
    for (int i = 0; i < TM; i++)
        #pragma unroll
        for (int j = 0; j < TN; j++) acc[i][j] = 0.f;

    int arow = tid / 4;            // 0..63
    int acol = (tid % 4) * 4;      // 0,4,8,12
    int brow = tid / 32;           // 0..7
    int bcol = (tid % 32) * 4;     // 0..124

    for (int k0 = 0; k0 < K; k0 += BK) {
        #pragma unroll
        for (int r = 0; r < 2; r++) {
            int m = arow + r * 64;
            int gr = rowBase + m;
            float4 v = make_float4(0.f, 0.f, 0.f, 0.f);
            if (gr < M) v = *reinterpret_cast<const float4*>(A + (size_t)gr * K + k0 + acol);
            As[acol + 0][m] = v.x; As[acol + 1][m] = v.y;
            As[acol + 2][m] = v.z; As[acol + 3][m] = v.w;
        }
        #pragma unroll
        for (int r = 0; r < 2; r++) {
            int kk = brow + r * 8;
            float4 v = *reinterpret_cast<const float4*>(B + (size_t)(k0 + kk) * OUTF + colBase + bcol);
            *reinterpret_cast<float4*>(&Bs[kk][bcol]) = v;
        }
        __syncthreads();
        #pragma unroll
        for (int kk = 0; kk < BK; kk++) {
            float af[TM], bf[TN];
            #pragma unroll
            for (int i = 0; i < TM; i++) af[i] = As[kk][ty * TM + i];
            #pragma unroll
            for (int j = 0; j < TN; j++) bf[j] = Bs[kk][tx * TN + j];
            #pragma unroll
            for (int i = 0; i < TM; i++)
                #pragma unroll
                for (int j = 0; j < TN; j++)
                    acc[i][j] += af[i] * bf[j];
        }
        __syncthreads();
    }
    #pragma unroll
    for (int i = 0; i < TM; i++) {
        int gr = rowBase + ty * TM + i;
        if (gr >= M) continue;
        #pragma unroll
        for (int j = 0; j < TN; j += 4) {
            *reinterpret_cast<float4*>(g_hp + (size_t)gr * OUTF + colBase + tx * TN + j) =
                make_float4(acc[i][j], acc[i][j + 1], acc[i][j + 2], acc[i][j + 3]);
        }
    }
}

// ---------------- 2: per-node logits s_src, s_dst ----------------
__global__ void node_dots_kernel(const float* __restrict__ a_src,
                                 const float* __restrict__ a_dst) {
    int warp = (blockIdx.x * blockDim.x + threadIdx.x) >> 5;
    int lane = threadIdx.x & 31;
    if (warp >= NN) return;
    const float* row = g_hp + (size_t)warp * OUTF;
    float rs[HD], rd[HD];
    #pragma unroll
    for (int h = 0; h < HD; h++) {
        float v1 = row[h * DD + lane], v2 = row[h * DD + 32 + lane];
        float as = v1 * a_src[h * DD + lane] + v2 * a_src[h * DD + 32 + lane];
        float ad = v1 * a_dst[h * DD + lane] + v2 * a_dst[h * DD + 32 + lane];
        #pragma unroll
        for (int o = 16; o; o >>= 1) {
            as += __shfl_xor_sync(0xffffffffu, as, o);
            ad += __shfl_xor_sync(0xffffffffu, ad, o);
        }
        rs[h] = as; rd[h] = ad;
    }
    if (lane == 0) {
        g_ssrc[warp] = make_float4(rs[0], rs[1], rs[2], rs[3]);
        g_sdst[warp] = make_float4(rd[0], rd[1], rd[2], rd[3]);
    }
}

// ---------------- 3: count in-degree (skip invalid ids) ----------------
__global__ void count_deg_kernel(const int* __restrict__ ei, const int* __restrict__ dst_sep) {
    int e = blockIdx.x * blockDim.x + threadIdx.x;
    if (e >= EE) return;
    int st = g_stride;
    const int* d_base = dst_sep ? dst_sep : ei + (size_t)EE * st;
    int u = d_base[(size_t)e * st];
    if (u >= 0 && u < NN) atomicAdd(&g_deg[u], 1);
}

// ---------------- 4: exclusive scan (single block, 1024 threads) ----------------
__global__ void scan_kernel() {
    __shared__ int warpsums[32];
    __shared__ int carrysh;
    int t = threadIdx.x, lane = t & 31, wid = t >> 5;
    if (t == 0) carrysh = 0;
    __syncthreads();
    for (int base = 0; base < NN; base += 1024) {
        int idx = base + t;
        int v = (idx < NN) ? g_deg[idx] : 0;
        int x = v;
        #pragma unroll
        for (int o = 1; o < 32; o <<= 1) {
            int y = __shfl_up_sync(0xffffffffu, x, o);
            if (lane >= o) x += y;
        }
        if (lane == 31) warpsums[wid] = x;
        __syncthreads();
        if (wid == 0) {
            int s = warpsums[lane];
            #pragma unroll
            for (int o = 1; o < 32; o <<= 1) {
                int y = __shfl_up_sync(0xffffffffu, s, o);
                if (lane >= o) s += y;
            }
            warpsums[lane] = s;
        }
        __syncthreads();
        int incl = x + (wid > 0 ? warpsums[wid - 1] : 0);
        int carry = carrysh;
        int excl = carry + incl - v;
        if (idx < NN) { g_off[idx] = excl; g_cursor[idx] = excl; }
        __syncthreads();
        if (t == 1023) carrysh = carry + incl;
        __syncthreads();
    }
}

// ---------------- 5: scatter edges into CSR (same validity rule as count) ----------------
__global__ void scatter_kernel(const int* __restrict__ ei, const int* __restrict__ dst_sep) {
    int e = blockIdx.x * blockDim.x + threadIdx.x;
    if (e >= EE) return;
    int st = g_stride;
    const int* s_base = ei;
    const int* d_base = dst_sep ? dst_sep : ei + (size_t)EE * st;
    int ud = d_base[(size_t)e * st];
    if (ud < 0 || ud >= NN) return;
    int us = s_base[(size_t)e * st];
    if (us < 0) us = 0;
    if (us >= NN) us = NN - 1;
    int p = atomicAdd(&g_cursor[ud], 1);
    if (p >= 0 && p < EE) g_csr[p] = us;
}

// ---------------- 6: per-dst-node softmax + aggregation ----------------
// blockDim = (64, 4): 64 threads (one per d), 4 nodes per block.
__global__ __launch_bounds__(256)
void aggregate_kernel(float* __restrict__ out) {
    int t = threadIdx.x;                 // 0..63 (d index)
    int yn = threadIdx.y;                // 0..3
    int node = blockIdx.x * 4 + yn;

    __shared__ float red_m[4][2][HD];
    __shared__ float red_z[4][2][HD];

    int start = 0, dn = 0;
    float sdv[HD] = {0.f, 0.f, 0.f, 0.f};
    if (node < NN) {
        start = g_off[node];
        dn = g_deg[node];
        float4 sd = g_sdst[node];
        sdv[0] = sd.x; sdv[1] = sd.y; sdv[2] = sd.z; sdv[3] = sd.w;
    }

    float m[HD], z[HD], acc[HD];
    #pragma unroll
    for (int h = 0; h < HD; h++) { m[h] = -1e30f; z[h] = 0.f; acc[h] = 0.f; }

    // phase 1: online (max, sumexp) over this thread's edge subset
    for (int i = t; i < dn; i += 64) {
        int s = g_csr[start + i];
        float4 ss = g_ssrc[s];
        float sv[HD] = {ss.x, ss.y, ss.z, ss.w};
        #pragma unroll
        for (int h = 0; h < HD; h++) {
            float x = sv[h] + sdv[h];
            x = fmaxf(x, 0.2f * x);                 // leaky relu 0.2
            if (x > m[h]) { z[h] = z[h] * __expf(m[h] - x) + 1.f; m[h] = x; }
            else          { z[h] += __expf(x - m[h]); }
        }
    }
    // warp-level merge
    #pragma unroll
    for (int h = 0; h < HD; h++) {
        #pragma unroll
        for (int o = 16; o; o >>= 1) {
            float mo = __shfl_xor_sync(0xffffffffu, m[h], o);
            float zo = __shfl_xor_sync(0xffffffffu, z[h], o);
            float mn = fmaxf(m[h], mo);
            z[h] = z[h] * __expf(m[h] - mn) + zo * __expf(mo - mn);
            m[h] = mn;
        }
    }
    int warp = t >> 5;
    if ((t & 31) == 0) {
        #pragma unroll
        for (int h = 0; h < HD; h++) { red_m[yn][warp][h] = m[h]; red_z[yn][warp][h] = z[h]; }
    }
    __syncthreads();
    float inv[HD];
    #pragma unroll
    for (int h = 0; h < HD; h++) {
        float m0 = red_m[yn][0][h], m1 = red_m[yn][1][h];
        float z0 = red_z[yn][0][h], z1 = red_z[yn][1][h];
        float mn = fmaxf(m0, m1);
        float zz = z0 * __expf(m0 - mn) + z1 * __expf(m1 - mn);
        m[h] = mn;
        inv[h] = (zz > 0.f) ? 1.f / zz : 0.f;
    }

    // phase 2: normalize & accumulate; all 64 threads walk the edge list together
    for (int i = 0; i < dn; i++) {
        int s = g_csr[start + i];
        float4 ss = g_ssrc[s];                      // broadcast
        float sv[HD] = {ss.x, ss.y, ss.z, ss.w};
        const float* hrow = g_hp + (size_t)s * OUTF;
        #pragma unroll
        for (int h = 0; h < HD; h++) {
            float x = sv[h] + sdv[h];
            x = fmaxf(x, 0.2f * x);
            float a = __expf(x - m[h]) * inv[h];
            acc[h] += a * hrow[h * DD + t];         // coalesced
        }
    }
    if (node < NN) {
        #pragma unroll
        for (int h = 0; h < HD; h++)
            out[(size_t)node * OUTF + h * DD + t] = acc[h];
    }
}

// ---------------- launch ----------------
extern "C" void kernel_launch(void* const* d_in, const int* in_sizes, int n_in,
                              void* d_out, int out_size) {
    const float* h     = nullptr;
    const int*   ei    = nullptr;   // combined (2,E)
    const int*   src2  = nullptr;
    const int*   dst2  = nullptr;
    const float* W     = nullptr;
    const float* a_src = nullptr;
    const float* a_dst = nullptr;

    for (int i = 0; i < n_in; i++) {
        long sz = in_sizes[i];
        if (sz == 12800000L)      h = (const float*)d_in[i];
        else if (sz == 65536L)    W = (const float*)d_in[i];
        else if (sz == 256L) {
            if (!a_src) a_src = (const float*)d_in[i];
            else        a_dst = (const float*)d_in[i];
        }
        else if (sz == 1600000L)  ei = (const int*)d_in[i];
        else if (sz == 800000L) {
            if (!src2) src2 = (const int*)d_in[i];
            else       dst2 = (const int*)d_in[i];
        }
    }
    // Positional fallback (metadata order: h, edge_index, W, a_src, a_dst)
    if (!h)                       h     = (const float*)d_in[0];
    if (!ei && !src2 && n_in > 1) ei    = (const int*)d_in[1];
    if (!W && n_in > 2)           W     = (const float*)d_in[2];
    if (!a_src && n_in > 3)       a_src = (const float*)d_in[3];
    if (!a_dst && n_in > 4)       a_dst = (const float*)d_in[4];

    const int* ebase = ei ? ei : src2;
    const int* dsep  = ei ? nullptr : dst2;
    float* out = (float*)d_out;

    detect_kernel<<<1, 32>>>(ebase);
    zero_deg_kernel<<<(NN + 255) / 256, 256>>>();

    dim3 ggrid(OUTF / BN, (NN + BM - 1) / BM);
    sgemm_kernel<<<ggrid, 256>>>(h, W, NN);

    node_dots_kernel<<<(NN * 32 + 127) / 128, 128>>>(a_src, a_dst);

    count_deg_kernel<<<(EE + 255) / 256, 256>>>(ebase, dsep);
    scan_kernel<<<1, 1024>>>();
    scatter_kernel<<<(EE + 255) / 256, 256>>>(ebase, dsep);

    dim3 ablock(64, 4);
    aggregate_kernel<<<(NN + 3) / 4, ablock>>>(out);
}

// round 6
// speedup vs baseline: 1.5791x; 1.5791x over previous
#include <cuda_runtime.h>
#include <cstdint>

// ---------------- Problem constants ----------------
#define NN 50000
#define EE 800000
#define KIN 256
#define HD 4
#define DD 64
#define OUTF (HD*DD)   // 256

// ---------------- Scratch (device globals; referenced ONLY from device code) ----------------
__device__ float  g_hp[(size_t)NN * OUTF];     // projected features [N,256] (~51.2MB, L2-resident)
__device__ float  g_wt[KIN * OUTF];            // W^T [N=256][K=256], K contiguous
__device__ float4 g_ssrc[NN];                  // per-node src logits
__device__ float4 g_sdst[NN];                  // per-node dst logits
__device__ float4 g_w[EE];                     // normalized edge weights per head (12.8MB)
__device__ int    g_deg[NN];
__device__ int    g_off[NN];
__device__ int    g_cursor[NN];
__device__ int    g_csr[EE];
__device__ int    g_stride;                    // 1 = int32 indices, 2 = int64 low word

// ---------------- detect int64 vs int32 edge_index ----------------
__global__ void detect_kernel(const int* __restrict__ ei) {
    if (blockIdx.x == 0 && threadIdx.x == 0) {
        int odd_nz = 0, even_nz = 0;
        for (int i = 0; i < 512; i++) {
            if (ei[2 * i + 1] != 0) odd_nz++;
            if (ei[2 * i] != 0)     even_nz++;
        }
        g_stride = (odd_nz == 0 && even_nz > 0) ? 2 : 1;
    }
}

// ---------------- zero degree ----------------
__global__ void zero_deg_kernel() {
    int i = blockIdx.x * blockDim.x + threadIdx.x;
    if (i < NN) g_deg[i] = 0;
}

// ---------------- transpose W: g_wt[n][k] = W[k][n] ----------------
__global__ void transpose_w_kernel(const float* __restrict__ W) {
    __shared__ float tile[32][33];
    int bx = blockIdx.x * 32, by = blockIdx.y * 32;
    int tx = threadIdx.x, ty = threadIdx.y;
    // read W[k][n]: k = by+ty.., n = bx+tx (coalesced)
    #pragma unroll
    for (int r = 0; r < 4; r++)
        tile[ty + r * 8][tx] = W[(size_t)(by + ty + r * 8) * OUTF + bx + tx];
    __syncthreads();
    // write g_wt[n][k]: n = bx+ty.., k = by+tx (coalesced)
    #pragma unroll
    for (int r = 0; r < 4; r++)
        g_wt[(size_t)(bx + ty + r * 8) * KIN + by + tx] = tile[tx][ty + r * 8];
}

// ---------------- tf32 tensor-core GEMM: g_hp[M,256] = A[M,256] @ W ----------------
#define GBM 128
#define GBN 128
#define GBK 32
#define LDK 36   // pad: bank = (row*36+col)%32 = (row*4+col)%32 -> conflict-free fragments

__device__ __forceinline__ uint32_t f2tf32(float f) {
    uint32_t u;
    asm("cvt.rna.tf32.f32 %0, %1;" : "=r"(u) : "f"(f));
    return u;
}

__device__ __forceinline__ void mma_tf32(float4& d,
                                         uint32_t a0, uint32_t a1, uint32_t a2, uint32_t a3,
                                         uint32_t b0, uint32_t b1) {
    asm volatile(
        "mma.sync.aligned.m16n8k8.row.col.f32.tf32.tf32.f32 "
        "{%0,%1,%2,%3}, {%4,%5,%6,%7}, {%8,%9}, {%0,%1,%2,%3};"
        : "+f"(d.x), "+f"(d.y), "+f"(d.z), "+f"(d.w)
        : "r"(a0), "r"(a1), "r"(a2), "r"(a3), "r"(b0), "r"(b1));
}

__global__ __launch_bounds__(256)
void tf32_gemm_kernel(const float* __restrict__ A, int M) {
    __shared__ float As[GBM * LDK];
    __shared__ float Bs[GBN * LDK];
    int tid  = threadIdx.x;
    int warp = tid >> 5, lane = tid & 31;
    int wm = warp & 1, wn = warp >> 1;          // 2 x 4 warp grid; warp tile 64x32
    int rowBase = blockIdx.y * GBM;
    int colBase = blockIdx.x * GBN;

    float4 acc[4][4];
    #pragma unroll
    for (int i = 0; i < 4; i++)
        #pragma unroll
        for (int j = 0; j < 4; j++) acc[i][j] = make_float4(0.f, 0.f, 0.f, 0.f);

    int la_row = tid >> 3;          // 0..31
    int la_col = (tid & 7) * 4;     // 0,4,..,28

    float4 pa[4], pb[4];
    // prefetch k0 = 0
    #pragma unroll
    for (int r = 0; r < 4; r++) {
        int gr = rowBase + la_row + r * 32;
        pa[r] = (gr < M) ? *reinterpret_cast<const float4*>(A + (size_t)gr * KIN + la_col)
                         : make_float4(0.f, 0.f, 0.f, 0.f);
        int gn = colBase + la_row + r * 32;     // < 256 always
        pb[r] = *reinterpret_cast<const float4*>(g_wt + (size_t)gn * KIN + la_col);
    }

    for (int k0 = 0; k0 < KIN; k0 += GBK) {
        #pragma unroll
        for (int r = 0; r < 4; r++) {
            *reinterpret_cast<float4*>(&As[(la_row + r * 32) * LDK + la_col]) = pa[r];
            *reinterpret_cast<float4*>(&Bs[(la_row + r * 32) * LDK + la_col]) = pb[r];
        }
        __syncthreads();
        if (k0 + GBK < KIN) {
            #pragma unroll
            for (int r = 0; r < 4; r++) {
                int gr = rowBase + la_row + r * 32;
                pa[r] = (gr < M) ? *reinterpret_cast<const float4*>(A + (size_t)gr * KIN + k0 + GBK + la_col)
                                 : make_float4(0.f, 0.f, 0.f, 0.f);
                int gn = colBase + la_row + r * 32;
                pb[r] = *reinterpret_cast<const float4*>(g_wt + (size_t)gn * KIN + k0 + GBK + la_col);
            }
        }
        #pragma unroll
        for (int ks = 0; ks < 4; ks++) {
            int kb = ks * 8;
            uint32_t af[4][4], bf[4][2];
            int g4 = lane >> 2, l4 = lane & 3;
            #pragma unroll
            for (int mt = 0; mt < 4; mt++) {
                int r0 = wm * 64 + mt * 16 + g4;
                af[mt][0] = f2tf32(As[ r0      * LDK + kb + l4    ]);
                af[mt][1] = f2tf32(As[(r0 + 8) * LDK + kb + l4    ]);
                af[mt][2] = f2tf32(As[ r0      * LDK + kb + l4 + 4]);
                af[mt][3] = f2tf32(As[(r0 + 8) * LDK + kb + l4 + 4]);
            }
            #pragma unroll
            for (int nt = 0; nt < 4; nt++) {
                int n0 = wn * 32 + nt * 8 + g4;
                bf[nt][0] = f2tf32(Bs[n0 * LDK + kb + l4    ]);
                bf[nt][1] = f2tf32(Bs[n0 * LDK + kb + l4 + 4]);
            }
            #pragma unroll
            for (int mt = 0; mt < 4; mt++)
                #pragma unroll
                for (int nt = 0; nt < 4; nt++)
                    mma_tf32(acc[mt][nt], af[mt][0], af[mt][1], af[mt][2], af[mt][3],
                             bf[nt][0], bf[nt][1]);
        }
        __syncthreads();
    }

    // epilogue: D layout c0:(g4, l4*2) c1:+1, c2:(g4+8, l4*2) c3:+1
    int g4 = lane >> 2, l4 = lane & 3;
    #pragma unroll
    for (int mt = 0; mt < 4; mt++) {
        int r = rowBase + wm * 64 + mt * 16 + g4;
        #pragma unroll
        for (int nt = 0; nt < 4; nt++) {
            int c = colBase + wn * 32 + nt * 8 + l4 * 2;
            if (r < M)
                *reinterpret_cast<float2*>(g_hp + (size_t)r * OUTF + c) =
                    make_float2(acc[mt][nt].x, acc[mt][nt].y);
            if (r + 8 < M)
                *reinterpret_cast<float2*>(g_hp + (size_t)(r + 8) * OUTF + c) =
                    make_float2(acc[mt][nt].z, acc[mt][nt].w);
        }
    }
}

// ---------------- per-node logits s_src, s_dst ----------------
__global__ void node_dots_kernel(const float* __restrict__ a_src,
                                 const float* __restrict__ a_dst) {
    int warp = (blockIdx.x * blockDim.x + threadIdx.x) >> 5;
    int lane = threadIdx.x & 31;
    if (warp >= NN) return;
    const float* row = g_hp + (size_t)warp * OUTF;
    float rs[HD], rd[HD];
    #pragma unroll
    for (int h = 0; h < HD; h++) {
        float v1 = row[h * DD + lane], v2 = row[h * DD + 32 + lane];
        float as = v1 * a_src[h * DD + lane] + v2 * a_src[h * DD + 32 + lane];
        float ad = v1 * a_dst[h * DD + lane] + v2 * a_dst[h * DD + 32 + lane];
        #pragma unroll
        for (int o = 16; o; o >>= 1) {
            as += __shfl_xor_sync(0xffffffffu, as, o);
            ad += __shfl_xor_sync(0xffffffffu, ad, o);
        }
        rs[h] = as; rd[h] = ad;
    }
    if (lane == 0) {
        g_ssrc[warp] = make_float4(rs[0], rs[1], rs[2], rs[3]);
        g_sdst[warp] = make_float4(rd[0], rd[1], rd[2], rd[3]);
    }
}

// ---------------- count in-degree ----------------
__global__ void count_deg_kernel(const int* __restrict__ ei, const int* __restrict__ dst_sep) {
    int e = blockIdx.x * blockDim.x + threadIdx.x;
    if (e >= EE) return;
    int st = g_stride;
    const int* d_base = dst_sep ? dst_sep : ei + (size_t)EE * st;
    int u = d_base[(size_t)e * st];
    if (u >= 0 && u < NN) atomicAdd(&g_deg[u], 1);
}

// ---------------- exclusive scan (single block) ----------------
__global__ void scan_kernel() {
    __shared__ int warpsums[32];
    __shared__ int carrysh;
    int t = threadIdx.x, lane = t & 31, wid = t >> 5;
    if (t == 0) carrysh = 0;
    __syncthreads();
    for (int base = 0; base < NN; base += 1024) {
        int idx = base + t;
        int v = (idx < NN) ? g_deg[idx] : 0;
        int x = v;
        #pragma unroll
        for (int o = 1; o < 32; o <<= 1) {
            int y = __shfl_up_sync(0xffffffffu, x, o);
            if (lane >= o) x += y;
        }
        if (lane == 31) warpsums[wid] = x;
        __syncthreads();
        if (wid == 0) {
            int s = warpsums[lane];
            #pragma unroll
            for (int o = 1; o < 32; o <<= 1) {
                int y = __shfl_up_sync(0xffffffffu, s, o);
                if (lane >= o) s += y;
            }
            warpsums[lane] = s;
        }
        __syncthreads();
        int incl = x + (wid > 0 ? warpsums[wid - 1] : 0);
        int carry = carrysh;
        int excl = carry + incl - v;
        if (idx < NN) { g_off[idx] = excl; g_cursor[idx] = excl; }
        __syncthreads();
        if (t == 1023) carrysh = carry + incl;
        __syncthreads();
    }
}

// ---------------- scatter edges into CSR ----------------
__global__ void scatter_kernel(const int* __restrict__ ei, const int* __restrict__ dst_sep) {
    int e = blockIdx.x * blockDim.x + threadIdx.x;
    if (e >= EE) return;
    int st = g_stride;
    const int* d_base = dst_sep ? dst_sep : ei + (size_t)EE * st;
    int ud = d_base[(size_t)e * st];
    if (ud < 0 || ud >= NN) return;
    int us = ei[(size_t)e * st];
    if (us < 0) us = 0;
    if (us >= NN) us = NN - 1;
    int p = atomicAdd(&g_cursor[ud], 1);
    if (p >= 0 && p < EE) g_csr[p] = us;
}

// ---------------- softmax stats + edge weights (warp per node) ----------------
__global__ __launch_bounds__(256)
void edge_weight_kernel() {
    int node = (blockIdx.x * blockDim.x + threadIdx.x) >> 5;
    int lane = threadIdx.x & 31;
    if (node >= NN) return;
    int start = g_off[node], dn = g_deg[node];
    if (dn == 0) return;
    float4 sd = g_sdst[node];
    float sdv[HD] = {sd.x, sd.y, sd.z, sd.w};

    float m[HD], z[HD];
    #pragma unroll
    for (int h = 0; h < HD; h++) { m[h] = -1e30f; z[h] = 0.f; }

    for (int i = lane; i < dn; i += 32) {
        int s = g_csr[start + i];
        float4 ss = g_ssrc[s];
        float sv[HD] = {ss.x, ss.y, ss.z, ss.w};
        #pragma unroll
        for (int h = 0; h < HD; h++) {
            float x = sv[h] + sdv[h];
            x = fmaxf(x, 0.2f * x);
            if (x > m[h]) { z[h] = z[h] * __expf(m[h] - x) + 1.f; m[h] = x; }
            else          { z[h] += __expf(x - m[h]); }
        }
    }
    #pragma unroll
    for (int h = 0; h < HD; h++) {
        #pragma unroll
        for (int o = 16; o; o >>= 1) {
            float mo = __shfl_xor_sync(0xffffffffu, m[h], o);
            float zo = __shfl_xor_sync(0xffffffffu, z[h], o);
            float mn = fmaxf(m[h], mo);
            z[h] = z[h] * __expf(m[h] - mn) + zo * __expf(mo - mn);
            m[h] = mn;
        }
    }
    float inv[HD];
    #pragma unroll
    for (int h = 0; h < HD; h++) inv[h] = (z[h] > 0.f) ? 1.f / z[h] : 0.f;

    for (int i = lane; i < dn; i += 32) {
        int s = g_csr[start + i];
        float4 ss = g_ssrc[s];
        float sv[HD] = {ss.x, ss.y, ss.z, ss.w};
        float w[HD];
        #pragma unroll
        for (int h = 0; h < HD; h++) {
            float x = sv[h] + sdv[h];
            x = fmaxf(x, 0.2f * x);
            w[h] = __expf(x - m[h]) * inv[h];
        }
        g_w[start + i] = make_float4(w[0], w[1], w[2], w[3]);
    }
}

// ---------------- aggregation: thread owns one float4 of the output row ----------------
__global__ __launch_bounds__(256)
void aggregate_kernel(float* __restrict__ out) {
    int t = threadIdx.x;                 // 0..63: float4 chunk index
    int yn = threadIdx.y;                // 0..3
    int node = blockIdx.x * 4 + yn;
    if (node >= NN) return;
    int start = g_off[node], dn = g_deg[node];
    int hq = t >> 4;                     // head owning this chunk

    float4 acc = make_float4(0.f, 0.f, 0.f, 0.f);
    int i = 0;
    for (; i + 1 < dn; i += 2) {
        int s0 = g_csr[start + i], s1 = g_csr[start + i + 1];
        float4 w0 = g_w[start + i], w1 = g_w[start + i + 1];
        float4 v0 = *reinterpret_cast<const float4*>(g_hp + (size_t)s0 * OUTF + t * 4);
        float4 v1 = *reinterpret_cast<const float4*>(g_hp + (size_t)s1 * OUTF + t * 4);
        float a0 = (&w0.x)[hq], a1 = (&w1.x)[hq];
        acc.x += a0 * v0.x + a1 * v1.x;
        acc.y += a0 * v0.y + a1 * v1.y;
        acc.z += a0 * v0.z + a1 * v1.z;
        acc.w += a0 * v0.w + a1 * v1.w;
    }
    if (i < dn) {
        int s0 = g_csr[start + i];
        float4 w0 = g_w[start + i];
        float4 v0 = *reinterpret_cast<const float4*>(g_hp + (size_t)s0 * OUTF + t * 4);
        float a0 = (&w0.x)[hq];
        acc.x += a0 * v0.x; acc.y += a0 * v0.y;
        acc.z += a0 * v0.z; acc.w += a0 * v0.w;
    }
    *reinterpret_cast<float4*>(out + (size_t)node * OUTF + t * 4) = acc;
}

// ---------------- launch ----------------
extern "C" void kernel_launch(void* const* d_in, const int* in_sizes, int n_in,
                              void* d_out, int out_size) {
    const float* h     = nullptr;
    const int*   ei    = nullptr;
    const int*   src2  = nullptr;
    const int*   dst2  = nullptr;
    const float* W     = nullptr;
    const float* a_src = nullptr;
    const float* a_dst = nullptr;

    for (int i = 0; i < n_in; i++) {
        long sz = in_sizes[i];
        if (sz == 12800000L)      h = (const float*)d_in[i];
        else if (sz == 65536L)    W = (const float*)d_in[i];
        else if (sz == 256L) {
            if (!a_src) a_src = (const float*)d_in[i];
            else        a_dst = (const float*)d_in[i];
        }
        else if (sz == 1600000L)  ei = (const int*)d_in[i];
        else if (sz == 800000L) {
            if (!src2) src2 = (const int*)d_in[i];
            else       dst2 = (const int*)d_in[i];
        }
    }
    if (!h)                       h     = (const float*)d_in[0];
    if (!ei && !src2 && n_in > 1) ei    = (const int*)d_in[1];
    if (!W && n_in > 2)           W     = (const float*)d_in[2];
    if (!a_src && n_in > 3)       a_src = (const float*)d_in[3];
    if (!a_dst && n_in > 4)       a_dst = (const float*)d_in[4];

    const int* ebase = ei ? ei : src2;
    const int* dsep  = ei ? nullptr : dst2;
    float* out = (float*)d_out;

    detect_kernel<<<1, 32>>>(ebase);
    zero_deg_kernel<<<(NN + 255) / 256, 256>>>();

    dim3 tblock(32, 8);
    transpose_w_kernel<<<dim3(8, 8), tblock>>>(W);

    dim3 ggrid(OUTF / GBN, (NN + GBM - 1) / GBM);
    tf32_gemm_kernel<<<ggrid, 256>>>(h, NN);

    node_dots_kernel<<<(NN * 32 + 127) / 128, 128>>>(a_src, a_dst);

    count_deg_kernel<<<(EE + 255) / 256, 256>>>(ebase, dsep);
    scan_kernel<<<1, 1024>>>();
    scatter_kernel<<<(EE + 255) / 256, 256>>>(ebase, dsep);

    edge_weight_kernel<<<(NN * 32 + 255) / 256, 256>>>();

    dim3 ablock(64, 4);
    aggregate_kernel<<<(NN + 3) / 4, ablock>>>(out);
}

// round 7
// speedup vs baseline: 1.7674x; 1.1193x over previous
#include <cuda_runtime.h>
#include <cstdint>

// ---------------- Problem constants ----------------
#define NN 50000
#define EE 800000
#define KIN 256
#define HD 4
#define DD 64
#define OUTF (HD*DD)   // 256

// ---------------- Scratch (device globals; referenced ONLY from device code) ----------------
__device__ float  g_hp[(size_t)NN * OUTF];     // projected features [N,256]
__device__ float  g_wt[KIN * OUTF];            // W^T, pre-rounded to tf32
__device__ float4 g_ssrc[NN];
__device__ float4 g_sdst[NN];
__device__ float4 g_w[EE];                     // un-normalized exp weights per head
__device__ float  g_z[NN * HD];                // per-node per-head partition sums
__device__ int    g_deg[NN];
__device__ int    g_off[NN];
__device__ int    g_cursor[NN];
__device__ int    g_csr[EE];
__device__ int    g_stride;

// ---------------- detect int64 vs int32 edge_index ----------------
__global__ void detect_kernel(const int* __restrict__ ei) {
    if (blockIdx.x == 0 && threadIdx.x == 0) {
        int odd_nz = 0, even_nz = 0;
        for (int i = 0; i < 512; i++) {
            if (ei[2 * i + 1] != 0) odd_nz++;
            if (ei[2 * i] != 0)     even_nz++;
        }
        g_stride = (odd_nz == 0 && even_nz > 0) ? 2 : 1;
    }
}

// ---------------- zero deg + z ----------------
__global__ void zero_kernel() {
    int i = blockIdx.x * blockDim.x + threadIdx.x;
    if (i < NN) g_deg[i] = 0;
    if (i < NN * HD) g_z[i] = 0.f;
}

__device__ __forceinline__ float tf32r(float f) {
    uint32_t u;
    asm("cvt.rna.tf32.f32 %0, %1;" : "=r"(u) : "f"(f));
    return __uint_as_float(u);
}

// ---------------- transpose W (+ tf32 pre-round): g_wt[n][k] = tf32(W[k][n]) ----------------
__global__ void transpose_w_kernel(const float* __restrict__ W) {
    __shared__ float tile[32][33];
    int bx = blockIdx.x * 32, by = blockIdx.y * 32;
    int tx = threadIdx.x, ty = threadIdx.y;
    #pragma unroll
    for (int r = 0; r < 4; r++)
        tile[ty + r * 8][tx] = W[(size_t)(by + ty + r * 8) * OUTF + bx + tx];
    __syncthreads();
    #pragma unroll
    for (int r = 0; r < 4; r++)
        g_wt[(size_t)(bx + ty + r * 8) * KIN + by + tx] = tf32r(tile[tx][ty + r * 8]);
}

// ---------------- tf32 tensor-core GEMM: g_hp[M,256] = A[M,256] @ W ----------------
#define GBM 128
#define GBN 128
#define GBK 32
#define LDK 36   // pad: bank = (row*4+col)%32 -> conflict-free

__device__ __forceinline__ void mma_tf32(float4& d,
                                         uint32_t a0, uint32_t a1, uint32_t a2, uint32_t a3,
                                         uint32_t b0, uint32_t b1) {
    asm volatile(
        "mma.sync.aligned.m16n8k8.row.col.f32.tf32.tf32.f32 "
        "{%0,%1,%2,%3}, {%4,%5,%6,%7}, {%8,%9}, {%0,%1,%2,%3};"
        : "+f"(d.x), "+f"(d.y), "+f"(d.z), "+f"(d.w)
        : "r"(a0), "r"(a1), "r"(a2), "r"(a3), "r"(b0), "r"(b1));
}

__global__ __launch_bounds__(256, 2)
void tf32_gemm_kernel(const float* __restrict__ A, int M) {
    __shared__ uint32_t As[GBM * LDK];
    __shared__ uint32_t Bs[GBN * LDK];
    int tid  = threadIdx.x;
    int warp = tid >> 5, lane = tid & 31;
    int wm = warp & 1, wn = warp >> 1;          // 2 x 4 warps; warp tile 64x32
    int rowBase = blockIdx.y * GBM;
    int colBase = blockIdx.x * GBN;

    float4 acc[4][4];
    #pragma unroll
    for (int i = 0; i < 4; i++)
        #pragma unroll
        for (int j = 0; j < 4; j++) acc[i][j] = make_float4(0.f, 0.f, 0.f, 0.f);

    int la_row = tid >> 3;
    int la_col = (tid & 7) * 4;

    float4 pa[4], pb[4];
    #pragma unroll
    for (int r = 0; r < 4; r++) {
        int gr = rowBase + la_row + r * 32;
        pa[r] = (gr < M) ? *reinterpret_cast<const float4*>(A + (size_t)gr * KIN + la_col)
                         : make_float4(0.f, 0.f, 0.f, 0.f);
        int gn = colBase + la_row + r * 32;
        pb[r] = *reinterpret_cast<const float4*>(g_wt + (size_t)gn * KIN + la_col);  // already tf32
    }

    for (int k0 = 0; k0 < KIN; k0 += GBK) {
        #pragma unroll
        for (int r = 0; r < 4; r++) {
            uint4 av;   // round A to tf32 here, once
            av.x = __float_as_uint(tf32r(pa[r].x));
            av.y = __float_as_uint(tf32r(pa[r].y));
            av.z = __float_as_uint(tf32r(pa[r].z));
            av.w = __float_as_uint(tf32r(pa[r].w));
            *reinterpret_cast<uint4*>(&As[(la_row + r * 32) * LDK + la_col]) = av;
            *reinterpret_cast<uint4*>(&Bs[(la_row + r * 32) * LDK + la_col]) =
                *reinterpret_cast<uint4*>(&pb[r]);
        }
        __syncthreads();
        if (k0 + GBK < KIN) {
            #pragma unroll
            for (int r = 0; r < 4; r++) {
                int gr = rowBase + la_row + r * 32;
                pa[r] = (gr < M) ? *reinterpret_cast<const float4*>(A + (size_t)gr * KIN + k0 + GBK + la_col)
                                 : make_float4(0.f, 0.f, 0.f, 0.f);
                int gn = colBase + la_row + r * 32;
                pb[r] = *reinterpret_cast<const float4*>(g_wt + (size_t)gn * KIN + k0 + GBK + la_col);
            }
        }
        int g4 = lane >> 2, l4 = lane & 3;
        #pragma unroll
        for (int ks = 0; ks < 4; ks++) {
            int kb = ks * 8;
            uint32_t af[4][4], bf[4][2];
            #pragma unroll
            for (int mt = 0; mt < 4; mt++) {
                int r0 = wm * 64 + mt * 16 + g4;
                af[mt][0] = As[ r0      * LDK + kb + l4    ];
                af[mt][1] = As[(r0 + 8) * LDK + kb + l4    ];
                af[mt][2] = As[ r0      * LDK + kb + l4 + 4];
                af[mt][3] = As[(r0 + 8) * LDK + kb + l4 + 4];
            }
            #pragma unroll
            for (int nt = 0; nt < 4; nt++) {
                int n0 = wn * 32 + nt * 8 + g4;
                bf[nt][0] = Bs[n0 * LDK + kb + l4    ];
                bf[nt][1] = Bs[n0 * LDK + kb + l4 + 4];
            }
            #pragma unroll
            for (int mt = 0; mt < 4; mt++)
                #pragma unroll
                for (int nt = 0; nt < 4; nt++)
                    mma_tf32(acc[mt][nt], af[mt][0], af[mt][1], af[mt][2], af[mt][3],
                             bf[nt][0], bf[nt][1]);
        }
        __syncthreads();
    }

    int g4 = lane >> 2, l4 = lane & 3;
    #pragma unroll
    for (int mt = 0; mt < 4; mt++) {
        int r = rowBase + wm * 64 + mt * 16 + g4;
        #pragma unroll
        for (int nt = 0; nt < 4; nt++) {
            int c = colBase + wn * 32 + nt * 8 + l4 * 2;
            if (r < M)
                *reinterpret_cast<float2*>(g_hp + (size_t)r * OUTF + c) =
                    make_float2(acc[mt][nt].x, acc[mt][nt].y);
            if (r + 8 < M)
                *reinterpret_cast<float2*>(g_hp + (size_t)(r + 8) * OUTF + c) =
                    make_float2(acc[mt][nt].z, acc[mt][nt].w);
        }
    }
}

// ---------------- per-node logits ----------------
__global__ void node_dots_kernel(const float* __restrict__ a_src,
                                 const float* __restrict__ a_dst) {
    int warp = (blockIdx.x * blockDim.x + threadIdx.x) >> 5;
    int lane = threadIdx.x & 31;
    if (warp >= NN) return;
    const float* row = g_hp + (size_t)warp * OUTF;
    float rs[HD], rd[HD];
    #pragma unroll
    for (int h = 0; h < HD; h++) {
        float v1 = row[h * DD + lane], v2 = row[h * DD + 32 + lane];
        float as = v1 * a_src[h * DD + lane] + v2 * a_src[h * DD + 32 + lane];
        float ad = v1 * a_dst[h * DD + lane] + v2 * a_dst[h * DD + 32 + lane];
        #pragma unroll
        for (int o = 16; o; o >>= 1) {
            as += __shfl_xor_sync(0xffffffffu, as, o);
            ad += __shfl_xor_sync(0xffffffffu, ad, o);
        }
        rs[h] = as; rd[h] = ad;
    }
    if (lane == 0) {
        g_ssrc[warp] = make_float4(rs[0], rs[1], rs[2], rs[3]);
        g_sdst[warp] = make_float4(rd[0], rd[1], rd[2], rd[3]);
    }
}

// ---------------- count in-degree ----------------
__global__ void count_deg_kernel(const int* __restrict__ ei, const int* __restrict__ dst_sep) {
    int e = blockIdx.x * blockDim.x + threadIdx.x;
    if (e >= EE) return;
    int st = g_stride;
    const int* d_base = dst_sep ? dst_sep : ei + (size_t)EE * st;
    int u = d_base[(size_t)e * st];
    if (u >= 0 && u < NN) atomicAdd(&g_deg[u], 1);
}

// ---------------- exclusive scan (single block) ----------------
__global__ void scan_kernel() {
    __shared__ int warpsums[32];
    __shared__ int carrysh;
    int t = threadIdx.x, lane = t & 31, wid = t >> 5;
    if (t == 0) carrysh = 0;
    __syncthreads();
    for (int base = 0; base < NN; base += 1024) {
        int idx = base + t;
        int v = (idx < NN) ? g_deg[idx] : 0;
        int x = v;
        #pragma unroll
        for (int o = 1; o < 32; o <<= 1) {
            int y = __shfl_up_sync(0xffffffffu, x, o);
            if (lane >= o) x += y;
        }
        if (lane == 31) warpsums[wid] = x;
        __syncthreads();
        if (wid == 0) {
            int s = warpsums[lane];
            #pragma unroll
            for (int o = 1; o < 32; o <<= 1) {
                int y = __shfl_up_sync(0xffffffffu, s, o);
                if (lane >= o) s += y;
            }
            warpsums[lane] = s;
        }
        __syncthreads();
        int incl = x + (wid > 0 ? warpsums[wid - 1] : 0);
        int carry = carrysh;
        int excl = carry + incl - v;
        if (idx < NN) { g_off[idx] = excl; g_cursor[idx] = excl; }
        __syncthreads();
        if (t == 1023) carrysh = carry + incl;
        __syncthreads();
    }
}

// ---------------- fused scatter: CSR + exp weights + partition sums ----------------
__global__ void scatter_fused_kernel(const int* __restrict__ ei, const int* __restrict__ dst_sep) {
    int e = blockIdx.x * blockDim.x + threadIdx.x;
    if (e >= EE) return;
    int st = g_stride;
    const int* d_base = dst_sep ? dst_sep : ei + (size_t)EE * st;
    int ud = d_base[(size_t)e * st];
    if (ud < 0 || ud >= NN) return;
    int us = ei[(size_t)e * st];
    if (us < 0) us = 0;
    if (us >= NN) us = NN - 1;

    float4 ss = g_ssrc[us];
    float4 sd = g_sdst[ud];
    float ex[HD];
    float sv[HD] = {ss.x, ss.y, ss.z, ss.w};
    float dv[HD] = {sd.x, sd.y, sd.z, sd.w};
    #pragma unroll
    for (int h = 0; h < HD; h++) {
        float x = sv[h] + dv[h];
        x = fmaxf(x, 0.2f * x);          // leaky relu
        ex[h] = __expf(x);               // logits are O(1); no max-shift needed
    }
    int p = atomicAdd(&g_cursor[ud], 1);
    if (p >= 0 && p < EE) {
        g_csr[p] = us;
        g_w[p] = make_float4(ex[0], ex[1], ex[2], ex[3]);
    }
    #pragma unroll
    for (int h = 0; h < HD; h++)
        atomicAdd(&g_z[ud * HD + h], ex[h]);
}

// ---------------- aggregation: thread owns one float4 of the output row ----------------
__global__ __launch_bounds__(256)
void aggregate_kernel(float* __restrict__ out) {
    int t = threadIdx.x;                 // 0..63: float4 chunk
    int yn = threadIdx.y;                // 0..3
    int node = blockIdx.x * 4 + yn;
    if (node >= NN) return;
    int start = g_off[node], dn = g_deg[node];
    int hq = t >> 4;

    float4 acc = make_float4(0.f, 0.f, 0.f, 0.f);
    int i = 0;
    for (; i + 3 < dn; i += 4) {
        int s0 = g_csr[start + i],     s1 = g_csr[start + i + 1];
        int s2 = g_csr[start + i + 2], s3 = g_csr[start + i + 3];
        float a0 = (&g_w[start + i    ].x)[hq];
        float a1 = (&g_w[start + i + 1].x)[hq];
        float a2 = (&g_w[start + i + 2].x)[hq];
        float a3 = (&g_w[start + i + 3].x)[hq];
        float4 v0 = *reinterpret_cast<const float4*>(g_hp + (size_t)s0 * OUTF + t * 4);
        float4 v1 = *reinterpret_cast<const float4*>(g_hp + (size_t)s1 * OUTF + t * 4);
        float4 v2 = *reinterpret_cast<const float4*>(g_hp + (size_t)s2 * OUTF + t * 4);
        float4 v3 = *reinterpret_cast<const float4*>(g_hp + (size_t)s3 * OUTF + t * 4);
        acc.x += a0 * v0.x + a1 * v1.x + a2 * v2.x + a3 * v3.x;
        acc.y += a0 * v0.y + a1 * v1.y + a2 * v2.y + a3 * v3.y;
        acc.z += a0 * v0.z + a1 * v1.z + a2 * v2.z + a3 * v3.z;
        acc.w += a0 * v0.w + a1 * v1.w + a2 * v2.w + a3 * v3.w;
    }
    for (; i < dn; i++) {
        int s0 = g_csr[start + i];
        float a0 = (&g_w[start + i].x)[hq];
        float4 v0 = *reinterpret_cast<const float4*>(g_hp + (size_t)s0 * OUTF + t * 4);
        acc.x += a0 * v0.x; acc.y += a0 * v0.y;
        acc.z += a0 * v0.z; acc.w += a0 * v0.w;
    }
    float z = g_z[node * HD + hq];
    float inv = 1.f / (z + 1e-16f);
    acc.x *= inv; acc.y *= inv; acc.z *= inv; acc.w *= inv;
    *reinterpret_cast<float4*>(out + (size_t)node * OUTF + t * 4) = acc;
}

// ---------------- launch ----------------
extern "C" void kernel_launch(void* const* d_in, const int* in_sizes, int n_in,
                              void* d_out, int out_size) {
    const float* h     = nullptr;
    const int*   ei    = nullptr;
    const int*   src2  = nullptr;
    const int*   dst2  = nullptr;
    const float* W     = nullptr;
    const float* a_src = nullptr;
    const float* a_dst = nullptr;

    for (int i = 0; i < n_in; i++) {
        long sz = in_sizes[i];
        if (sz == 12800000L)      h = (const float*)d_in[i];
        else if (sz == 65536L)    W = (const float*)d_in[i];
        else if (sz == 256L) {
            if (!a_src) a_src = (const float*)d_in[i];
            else        a_dst = (const float*)d_in[i];
        }
        else if (sz == 1600000L)  ei = (const int*)d_in[i];
        else if (sz == 800000L) {
            if (!src2) src2 = (const int*)d_in[i];
            else       dst2 = (const int*)d_in[i];
        }
    }
    if (!h)                       h     = (const float*)d_in[0];
    if (!ei && !src2 && n_in > 1) ei    = (const int*)d_in[1];
    if (!W && n_in > 2)           W     = (const float*)d_in[2];
    if (!a_src && n_in > 3)       a_src = (const float*)d_in[3];
    if (!a_dst && n_in > 4)       a_dst = (const float*)d_in[4];

    const int* ebase = ei ? ei : src2;
    const int* dsep  = ei ? nullptr : dst2;
    float* out = (float*)d_out;

    detect_kernel<<<1, 32>>>(ebase);
    zero_kernel<<<(NN * HD + 255) / 256, 256>>>();

    dim3 tblock(32, 8);
    transpose_w_kernel<<<dim3(8, 8), tblock>>>(W);

    dim3 ggrid(OUTF / GBN, (NN + GBM - 1) / GBM);
    tf32_gemm_kernel<<<ggrid, 256>>>(h, NN);

    node_dots_kernel<<<(NN * 32 + 127) / 128, 128>>>(a_src, a_dst);

    count_deg_kernel<<<(EE + 255) / 256, 256>>>(ebase, dsep);
    scan_kernel<<<1, 1024>>>();
    scatter_fused_kernel<<<(EE + 255) / 256, 256>>>(ebase, dsep);

    dim3 ablock(64, 4);
    aggregate_kernel<<<(NN + 3) / 4, ablock>>>(out);
}

// round 8
// speedup vs baseline: 2.1178x; 1.1982x over previous
#include <cuda_runtime.h>
#include <cstdint>

// ---------------- Problem constants ----------------
#define NN 50000
#define EE 800000
#define KIN 256
#define HD 4
#define DD 64
#define OUTF (HD*DD)   // 256

// ---------------- Scratch (device globals; referenced ONLY from device code) ----------------
__device__ float  g_hp[(size_t)NN * OUTF];     // projected features [N,256]
__device__ float  g_wt[KIN * OUTF];            // W^T, pre-rounded to tf32
__device__ float4 g_ssrc[NN];
__device__ float4 g_sdst[NN];
__device__ int    g_deg[NN];
__device__ int    g_off[NN];
__device__ int    g_cursor[NN];
__device__ int    g_csr[EE];
__device__ int    g_stride;

// ---------------- detect int64 vs int32 edge_index ----------------
__global__ void detect_kernel(const int* __restrict__ ei) {
    if (blockIdx.x == 0 && threadIdx.x == 0) {
        int odd_nz = 0, even_nz = 0;
        for (int i = 0; i < 512; i++) {
            if (ei[2 * i + 1] != 0) odd_nz++;
            if (ei[2 * i] != 0)     even_nz++;
        }
        g_stride = (odd_nz == 0 && even_nz > 0) ? 2 : 1;
    }
}

// ---------------- zero degree ----------------
__global__ void zero_deg_kernel() {
    int i = blockIdx.x * blockDim.x + threadIdx.x;
    if (i < NN) g_deg[i] = 0;
}

__device__ __forceinline__ float tf32r(float f) {
    uint32_t u;
    asm("cvt.rna.tf32.f32 %0, %1;" : "=r"(u) : "f"(f));
    return __uint_as_float(u);
}

// ---------------- transpose W (+ tf32 pre-round): g_wt[n][k] = tf32(W[k][n]) ----------------
__global__ void transpose_w_kernel(const float* __restrict__ W) {
    __shared__ float tile[32][33];
    int bx = blockIdx.x * 32, by = blockIdx.y * 32;
    int tx = threadIdx.x, ty = threadIdx.y;
    #pragma unroll
    for (int r = 0; r < 4; r++)
        tile[ty + r * 8][tx] = W[(size_t)(by + ty + r * 8) * OUTF + bx + tx];
    __syncthreads();
    #pragma unroll
    for (int r = 0; r < 4; r++)
        g_wt[(size_t)(bx + ty + r * 8) * KIN + by + tx] = tf32r(tile[tx][ty + r * 8]);
}

// ---------------- tf32 tensor-core GEMM: g_hp[M,256] = A[M,256] @ W ----------------
#define GBM 128
#define GBN 128
#define GBK 32
#define LDK 36

__device__ __forceinline__ void mma_tf32(float4& d,
                                         uint32_t a0, uint32_t a1, uint32_t a2, uint32_t a3,
                                         uint32_t b0, uint32_t b1) {
    asm volatile(
        "mma.sync.aligned.m16n8k8.row.col.f32.tf32.tf32.f32 "
        "{%0,%1,%2,%3}, {%4,%5,%6,%7}, {%8,%9}, {%0,%1,%2,%3};"
        : "+f"(d.x), "+f"(d.y), "+f"(d.z), "+f"(d.w)
        : "r"(a0), "r"(a1), "r"(a2), "r"(a3), "r"(b0), "r"(b1));
}

__global__ __launch_bounds__(256, 2)
void tf32_gemm_kernel(const float* __restrict__ A, int M) {
    __shared__ uint32_t As[GBM * LDK];
    __shared__ uint32_t Bs[GBN * LDK];
    int tid  = threadIdx.x;
    int warp = tid >> 5, lane = tid & 31;
    int wm = warp & 1, wn = warp >> 1;
    int rowBase = blockIdx.y * GBM;
    int colBase = blockIdx.x * GBN;

    float4 acc[4][4];
    #pragma unroll
    for (int i = 0; i < 4; i++)
        #pragma unroll
        for (int j = 0; j < 4; j++) acc[i][j] = make_float4(0.f, 0.f, 0.f, 0.f);

    int la_row = tid >> 3;
    int la_col = (tid & 7) * 4;

    float4 pa[4], pb[4];
    #pragma unroll
    for (int r = 0; r < 4; r++) {
        int gr = rowBase + la_row + r * 32;
        pa[r] = (gr < M) ? *reinterpret_cast<const float4*>(A + (size_t)gr * KIN + la_col)
                         : make_float4(0.f, 0.f, 0.f, 0.f);
        int gn = colBase + la_row + r * 32;
        pb[r] = *reinterpret_cast<const float4*>(g_wt + (size_t)gn * KIN + la_col);
    }

    for (int k0 = 0; k0 < KIN; k0 += GBK) {
        #pragma unroll
        for (int r = 0; r < 4; r++) {
            uint4 av;
            av.x = __float_as_uint(tf32r(pa[r].x));
            av.y = __float_as_uint(tf32r(pa[r].y));
            av.z = __float_as_uint(tf32r(pa[r].z));
            av.w = __float_as_uint(tf32r(pa[r].w));
            *reinterpret_cast<uint4*>(&As[(la_row + r * 32) * LDK + la_col]) = av;
            *reinterpret_cast<uint4*>(&Bs[(la_row + r * 32) * LDK + la_col]) =
                *reinterpret_cast<uint4*>(&pb[r]);
        }
        __syncthreads();
        if (k0 + GBK < KIN) {
            #pragma unroll
            for (int r = 0; r < 4; r++) {
                int gr = rowBase + la_row + r * 32;
                pa[r] = (gr < M) ? *reinterpret_cast<const float4*>(A + (size_t)gr * KIN + k0 + GBK + la_col)
                                 : make_float4(0.f, 0.f, 0.f, 0.f);
                int gn = colBase + la_row + r * 32;
                pb[r] = *reinterpret_cast<const float4*>(g_wt + (size_t)gn * KIN + k0 + GBK + la_col);
            }
        }
        int g4 = lane >> 2, l4 = lane & 3;
        #pragma unroll
        for (int ks = 0; ks < 4; ks++) {
            int kb = ks * 8;
            uint32_t af[4][4], bf[4][2];
            #pragma unroll
            for (int mt = 0; mt < 4; mt++) {
                int r0 = wm * 64 + mt * 16 + g4;
                af[mt][0] = As[ r0      * LDK + kb + l4    ];
                af[mt][1] = As[(r0 + 8) * LDK + kb + l4    ];
                af[mt][2] = As[ r0      * LDK + kb + l4 + 4];
                af[mt][3] = As[(r0 + 8) * LDK + kb + l4 + 4];
            }
            #pragma unroll
            for (int nt = 0; nt < 4; nt++) {
                int n0 = wn * 32 + nt * 8 + g4;
                bf[nt][0] = Bs[n0 * LDK + kb + l4    ];
                bf[nt][1] = Bs[n0 * LDK + kb + l4 + 4];
            }
            #pragma unroll
            for (int mt = 0; mt < 4; mt++)
                #pragma unroll
                for (int nt = 0; nt < 4; nt++)
                    mma_tf32(acc[mt][nt], af[mt][0], af[mt][1], af[mt][2], af[mt][3],
                             bf[nt][0], bf[nt][1]);
        }
        __syncthreads();
    }

    int g4 = lane >> 2, l4 = lane & 3;
    #pragma unroll
    for (int mt = 0; mt < 4; mt++) {
        int r = rowBase + wm * 64 + mt * 16 + g4;
        #pragma unroll
        for (int nt = 0; nt < 4; nt++) {
            int c = colBase + wn * 32 + nt * 8 + l4 * 2;
            if (r < M)
                *reinterpret_cast<float2*>(g_hp + (size_t)r * OUTF + c) =
                    make_float2(acc[mt][nt].x, acc[mt][nt].y);
            if (r + 8 < M)
                *reinterpret_cast<float2*>(g_hp + (size_t)(r + 8) * OUTF + c) =
                    make_float2(acc[mt][nt].z, acc[mt][nt].w);
        }
    }
}

// ---------------- per-node logits ----------------
__global__ void node_dots_kernel(const float* __restrict__ a_src,
                                 const float* __restrict__ a_dst) {
    int warp = (blockIdx.x * blockDim.x + threadIdx.x) >> 5;
    int lane = threadIdx.x & 31;
    if (warp >= NN) return;
    const float* row = g_hp + (size_t)warp * OUTF;
    float rs[HD], rd[HD];
    #pragma unroll
    for (int h = 0; h < HD; h++) {
        float v1 = row[h * DD + lane], v2 = row[h * DD + 32 + lane];
        float as = v1 * a_src[h * DD + lane] + v2 * a_src[h * DD + 32 + lane];
        float ad = v1 * a_dst[h * DD + lane] + v2 * a_dst[h * DD + 32 + lane];
        #pragma unroll
        for (int o = 16; o; o >>= 1) {
            as += __shfl_xor_sync(0xffffffffu, as, o);
            ad += __shfl_xor_sync(0xffffffffu, ad, o);
        }
        rs[h] = as; rd[h] = ad;
    }
    if (lane == 0) {
        g_ssrc[warp] = make_float4(rs[0], rs[1], rs[2], rs[3]);
        g_sdst[warp] = make_float4(rd[0], rd[1], rd[2], rd[3]);
    }
}

// ---------------- count in-degree ----------------
__global__ void count_deg_kernel(const int* __restrict__ ei, const int* __restrict__ dst_sep) {
    int e = blockIdx.x * blockDim.x + threadIdx.x;
    if (e >= EE) return;
    int st = g_stride;
    const int* d_base = dst_sep ? dst_sep : ei + (size_t)EE * st;
    int u = d_base[(size_t)e * st];
    if (u >= 0 && u < NN) atomicAdd(&g_deg[u], 1);
}

// ---------------- exclusive scan (single block) ----------------
__global__ void scan_kernel() {
    __shared__ int warpsums[32];
    __shared__ int carrysh;
    int t = threadIdx.x, lane = t & 31, wid = t >> 5;
    if (t == 0) carrysh = 0;
    __syncthreads();
    for (int base = 0; base < NN; base += 1024) {
        int idx = base + t;
        int v = (idx < NN) ? g_deg[idx] : 0;
        int x = v;
        #pragma unroll
        for (int o = 1; o < 32; o <<= 1) {
            int y = __shfl_up_sync(0xffffffffu, x, o);
            if (lane >= o) x += y;
        }
        if (lane == 31) warpsums[wid] = x;
        __syncthreads();
        if (wid == 0) {
            int s = warpsums[lane];
            #pragma unroll
            for (int o = 1; o < 32; o <<= 1) {
                int y = __shfl_up_sync(0xffffffffu, s, o);
                if (lane >= o) s += y;
            }
            warpsums[lane] = s;
        }
        __syncthreads();
        int incl = x + (wid > 0 ? warpsums[wid - 1] : 0);
        int carry = carrysh;
        int excl = carry + incl - v;
        if (idx < NN) { g_off[idx] = excl; g_cursor[idx] = excl; }
        __syncthreads();
        if (t == 1023) carrysh = carry + incl;
        __syncthreads();
    }
}

// ---------------- pure CSR scatter (no dependence on GEMM path) ----------------
__global__ void scatter_kernel(const int* __restrict__ ei, const int* __restrict__ dst_sep) {
    int e = blockIdx.x * blockDim.x + threadIdx.x;
    if (e >= EE) return;
    int st = g_stride;
    const int* d_base = dst_sep ? dst_sep : ei + (size_t)EE * st;
    int ud = d_base[(size_t)e * st];
    if (ud < 0 || ud >= NN) return;
    int us = ei[(size_t)e * st];
    if (us < 0) us = 0;
    if (us >= NN) us = NN - 1;
    int p = atomicAdd(&g_cursor[ud], 1);
    if (p >= 0 && p < EE) g_csr[p] = us;
}

// ---------------- fused softmax + aggregation (single pass over edges) ----------------
// blockDim (64,4): thread owns one float4 chunk; accumulates unnormalized sum
// and the partition sum z for its head simultaneously; scales at the end.
__global__ __launch_bounds__(256)
void aggregate_fused_kernel(float* __restrict__ out) {
    int t = threadIdx.x;                 // 0..63: float4 chunk
    int yn = threadIdx.y;
    int node = blockIdx.x * 4 + yn;
    if (node >= NN) return;
    int start = g_off[node], dn = g_deg[node];
    int hq = t >> 4;
    float sdv = (&g_sdst[node].x)[hq];

    float4 acc = make_float4(0.f, 0.f, 0.f, 0.f);
    float z = 0.f;
    int i = 0;
    for (; i + 1 < dn; i += 2) {
        int s0 = g_csr[start + i], s1 = g_csr[start + i + 1];
        float x0 = (&g_ssrc[s0].x)[hq] + sdv;
        float x1 = (&g_ssrc[s1].x)[hq] + sdv;
        x0 = fmaxf(x0, 0.2f * x0);
        x1 = fmaxf(x1, 0.2f * x1);
        float e0 = __expf(x0), e1 = __expf(x1);
        float4 v0 = *reinterpret_cast<const float4*>(g_hp + (size_t)s0 * OUTF + t * 4);
        float4 v1 = *reinterpret_cast<const float4*>(g_hp + (size_t)s1 * OUTF + t * 4);
        z += e0 + e1;
        acc.x += e0 * v0.x + e1 * v1.x;
        acc.y += e0 * v0.y + e1 * v1.y;
        acc.z += e0 * v0.z + e1 * v1.z;
        acc.w += e0 * v0.w + e1 * v1.w;
    }
    if (i < dn) {
        int s0 = g_csr[start + i];
        float x0 = (&g_ssrc[s0].x)[hq] + sdv;
        x0 = fmaxf(x0, 0.2f * x0);
        float e0 = __expf(x0);
        float4 v0 = *reinterpret_cast<const float4*>(g_hp + (size_t)s0 * OUTF + t * 4);
        z += e0;
        acc.x += e0 * v0.x; acc.y += e0 * v0.y;
        acc.z += e0 * v0.z; acc.w += e0 * v0.w;
    }
    float inv = 1.f / (z + 1e-16f);
    acc.x *= inv; acc.y *= inv; acc.z *= inv; acc.w *= inv;
    *reinterpret_cast<float4*>(out + (size_t)node * OUTF + t * 4) = acc;
}

// ---------------- launch ----------------
extern "C" void kernel_launch(void* const* d_in, const int* in_sizes, int n_in,
                              void* d_out, int out_size) {
    const float* h     = nullptr;
    const int*   ei    = nullptr;
    const int*   src2  = nullptr;
    const int*   dst2  = nullptr;
    const float* W     = nullptr;
    const float* a_src = nullptr;
    const float* a_dst = nullptr;

    for (int i = 0; i < n_in; i++) {
        long sz = in_sizes[i];
        if (sz == 12800000L)      h = (const float*)d_in[i];
        else if (sz == 65536L)    W = (const float*)d_in[i];
        else if (sz == 256L) {
            if (!a_src) a_src = (const float*)d_in[i];
            else        a_dst = (const float*)d_in[i];
        }
        else if (sz == 1600000L)  ei = (const int*)d_in[i];
        else if (sz == 800000L) {
            if (!src2) src2 = (const int*)d_in[i];
            else       dst2 = (const int*)d_in[i];
        }
    }
    if (!h)                       h     = (const float*)d_in[0];
    if (!ei && !src2 && n_in > 1) ei    = (const int*)d_in[1];
    if (!W && n_in > 2)           W     = (const float*)d_in[2];
    if (!a_src && n_in > 3)       a_src = (const float*)d_in[3];
    if (!a_dst && n_in > 4)       a_dst = (const float*)d_in[4];

    const int* ebase = ei ? ei : src2;
    const int* dsep  = ei ? nullptr : dst2;
    float* out = (float*)d_out;

    // Fresh side-stream + events each call (host-side handles only; identical
    // device work every call; event fork/join is graph-capturable topology).
    cudaStream_t s2 = 0;
    cudaEvent_t ev_fork = nullptr, ev_join = nullptr;
    bool forked = (cudaStreamCreateWithFlags(&s2, cudaStreamNonBlocking) == cudaSuccess) &&
                  (cudaEventCreateWithFlags(&ev_fork, cudaEventDisableTiming) == cudaSuccess) &&
                  (cudaEventCreateWithFlags(&ev_join, cudaEventDisableTiming) == cudaSuccess);

    detect_kernel<<<1, 32>>>(ebase);

    if (forked) {
        cudaEventRecord(ev_fork, 0);
        cudaStreamWaitEvent(s2, ev_fork, 0);
    }
    cudaStream_t sb = forked ? s2 : 0;

    // CSR chain (independent of GEMM) on side stream
    zero_deg_kernel<<<(NN + 255) / 256, 256, 0, sb>>>();
    count_deg_kernel<<<(EE + 255) / 256, 256, 0, sb>>>(ebase, dsep);
    scan_kernel<<<1, 1024, 0, sb>>>();
    scatter_kernel<<<(EE + 255) / 256, 256, 0, sb>>>(ebase, dsep);

    // GEMM chain on main stream (overlaps with CSR chain)
    dim3 tblock(32, 8);
    transpose_w_kernel<<<dim3(8, 8), tblock>>>(W);
    dim3 ggrid(OUTF / GBN, (NN + GBM - 1) / GBM);
    tf32_gemm_kernel<<<ggrid, 256>>>(h, NN);
    node_dots_kernel<<<(NN * 32 + 127) / 128, 128>>>(a_src, a_dst);

    if (forked) {
        cudaEventRecord(ev_join, s2);
        cudaStreamWaitEvent(0, ev_join, 0);
    }

    dim3 ablock(64, 4);
    aggregate_fused_kernel<<<(NN + 3) / 4, ablock>>>(out);
}

// round 9
// speedup vs baseline: 2.3778x; 1.1228x over previous
#include <cuda_runtime.h>
#include <cstdint>

// ---------------- Problem constants ----------------
#define NN 50000
#define EE 800000
#define KIN 256
#define HD 4
#define DD 64
#define OUTF (HD*DD)   // 256
#define SCAN_NB ((NN + 1023) / 1024)   // 49

// ---------------- Scratch (device globals; referenced ONLY from device code) ----------------
__device__ float  g_hp[(size_t)NN * OUTF];
__device__ float  g_wt[KIN * OUTF];
__device__ float4 g_ssrc[NN];
__device__ float4 g_sdst[NN];
__device__ int    g_deg[NN];
__device__ int    g_off[NN];
__device__ int    g_cursor[NN];
__device__ int    g_csr[EE];
__device__ int    g_bsum[SCAN_NB];
__device__ int    g_boff[SCAN_NB];
__device__ int    g_stride;

// ---------------- detect int64 vs int32 edge_index ----------------
__global__ void detect_kernel(const int* __restrict__ ei) {
    if (blockIdx.x == 0 && threadIdx.x == 0) {
        int odd_nz = 0, even_nz = 0;
        for (int i = 0; i < 512; i++) {
            if (ei[2 * i + 1] != 0) odd_nz++;
            if (ei[2 * i] != 0)     even_nz++;
        }
        g_stride = (odd_nz == 0 && even_nz > 0) ? 2 : 1;
    }
}

// ---------------- zero degree ----------------
__global__ void zero_deg_kernel() {
    int i = blockIdx.x * blockDim.x + threadIdx.x;
    if (i < NN) g_deg[i] = 0;
}

__device__ __forceinline__ float tf32r(float f) {
    uint32_t u;
    asm("cvt.rna.tf32.f32 %0, %1;" : "=r"(u) : "f"(f));
    return __uint_as_float(u);
}

// ---------------- transpose W (+ tf32 pre-round) ----------------
__global__ void transpose_w_kernel(const float* __restrict__ W) {
    __shared__ float tile[32][33];
    int bx = blockIdx.x * 32, by = blockIdx.y * 32;
    int tx = threadIdx.x, ty = threadIdx.y;
    #pragma unroll
    for (int r = 0; r < 4; r++)
        tile[ty + r * 8][tx] = W[(size_t)(by + ty + r * 8) * OUTF + bx + tx];
    __syncthreads();
    #pragma unroll
    for (int r = 0; r < 4; r++)
        g_wt[(size_t)(bx + ty + r * 8) * KIN + by + tx] = tf32r(tile[tx][ty + r * 8]);
}

// ---------------- tf32 tensor-core GEMM ----------------
#define GBM 128
#define GBN 128
#define GBK 32
#define LDK 36

__device__ __forceinline__ void mma_tf32(float4& d,
                                         uint32_t a0, uint32_t a1, uint32_t a2, uint32_t a3,
                                         uint32_t b0, uint32_t b1) {
    asm volatile(
        "mma.sync.aligned.m16n8k8.row.col.f32.tf32.tf32.f32 "
        "{%0,%1,%2,%3}, {%4,%5,%6,%7}, {%8,%9}, {%0,%1,%2,%3};"
        : "+f"(d.x), "+f"(d.y), "+f"(d.z), "+f"(d.w)
        : "r"(a0), "r"(a1), "r"(a2), "r"(a3), "r"(b0), "r"(b1));
}

__global__ __launch_bounds__(256, 2)
void tf32_gemm_kernel(const float* __restrict__ A, int M) {
    __shared__ uint32_t As[GBM * LDK];
    __shared__ uint32_t Bs[GBN * LDK];
    int tid  = threadIdx.x;
    int warp = tid >> 5, lane = tid & 31;
    int wm = warp & 1, wn = warp >> 1;
    int rowBase = blockIdx.y * GBM;
    int colBase = blockIdx.x * GBN;

    float4 acc[4][4];
    #pragma unroll
    for (int i = 0; i < 4; i++)
        #pragma unroll
        for (int j = 0; j < 4; j++) acc[i][j] = make_float4(0.f, 0.f, 0.f, 0.f);

    int la_row = tid >> 3;
    int la_col = (tid & 7) * 4;

    float4 pa[4], pb[4];
    #pragma unroll
    for (int r = 0; r < 4; r++) {
        int gr = rowBase + la_row + r * 32;
        pa[r] = (gr < M) ? *reinterpret_cast<const float4*>(A + (size_t)gr * KIN + la_col)
                         : make_float4(0.f, 0.f, 0.f, 0.f);
        int gn = colBase + la_row + r * 32;
        pb[r] = *reinterpret_cast<const float4*>(g_wt + (size_t)gn * KIN + la_col);
    }

    for (int k0 = 0; k0 < KIN; k0 += GBK) {
        #pragma unroll
        for (int r = 0; r < 4; r++) {
            uint4 av;
            av.x = __float_as_uint(tf32r(pa[r].x));
            av.y = __float_as_uint(tf32r(pa[r].y));
            av.z = __float_as_uint(tf32r(pa[r].z));
            av.w = __float_as_uint(tf32r(pa[r].w));
            *reinterpret_cast<uint4*>(&As[(la_row + r * 32) * LDK + la_col]) = av;
            *reinterpret_cast<uint4*>(&Bs[(la_row + r * 32) * LDK + la_col]) =
                *reinterpret_cast<uint4*>(&pb[r]);
        }
        __syncthreads();
        if (k0 + GBK < KIN) {
            #pragma unroll
            for (int r = 0; r < 4; r++) {
                int gr = rowBase + la_row + r * 32;
                pa[r] = (gr < M) ? *reinterpret_cast<const float4*>(A + (size_t)gr * KIN + k0 + GBK + la_col)
                                 : make_float4(0.f, 0.f, 0.f, 0.f);
                int gn = colBase + la_row + r * 32;
                pb[r] = *reinterpret_cast<const float4*>(g_wt + (size_t)gn * KIN + k0 + GBK + la_col);
            }
        }
        int g4 = lane >> 2, l4 = lane & 3;
        #pragma unroll
        for (int ks = 0; ks < 4; ks++) {
            int kb = ks * 8;
            uint32_t af[4][4], bf[4][2];
            #pragma unroll
            for (int mt = 0; mt < 4; mt++) {
                int r0 = wm * 64 + mt * 16 + g4;
                af[mt][0] = As[ r0      * LDK + kb + l4    ];
                af[mt][1] = As[(r0 + 8) * LDK + kb + l4    ];
                af[mt][2] = As[ r0      * LDK + kb + l4 + 4];
                af[mt][3] = As[(r0 + 8) * LDK + kb + l4 + 4];
            }
            #pragma unroll
            for (int nt = 0; nt < 4; nt++) {
                int n0 = wn * 32 + nt * 8 + g4;
                bf[nt][0] = Bs[n0 * LDK + kb + l4    ];
                bf[nt][1] = Bs[n0 * LDK + kb + l4 + 4];
            }
            #pragma unroll
            for (int mt = 0; mt < 4; mt++)
                #pragma unroll
                for (int nt = 0; nt < 4; nt++)
                    mma_tf32(acc[mt][nt], af[mt][0], af[mt][1], af[mt][2], af[mt][3],
                             bf[nt][0], bf[nt][1]);
        }
        __syncthreads();
    }

    int g4 = lane >> 2, l4 = lane & 3;
    #pragma unroll
    for (int mt = 0; mt < 4; mt++) {
        int r = rowBase + wm * 64 + mt * 16 + g4;
        #pragma unroll
        for (int nt = 0; nt < 4; nt++) {
            int c = colBase + wn * 32 + nt * 8 + l4 * 2;
            if (r < M)
                *reinterpret_cast<float2*>(g_hp + (size_t)r * OUTF + c) =
                    make_float2(acc[mt][nt].x, acc[mt][nt].y);
            if (r + 8 < M)
                *reinterpret_cast<float2*>(g_hp + (size_t)(r + 8) * OUTF + c) =
                    make_float2(acc[mt][nt].z, acc[mt][nt].w);
        }
    }
}

// ---------------- per-node logits (float4 loads + segmented reduce) ----------------
__global__ void node_dots_kernel(const float* __restrict__ a_src,
                                 const float* __restrict__ a_dst) {
    int warp = (blockIdx.x * blockDim.x + threadIdx.x) >> 5;
    int lane = threadIdx.x & 31;
    if (warp >= NN) return;
    const float4* row = reinterpret_cast<const float4*>(g_hp + (size_t)warp * OUTF);
    const float4* as4 = reinterpret_cast<const float4*>(a_src);
    const float4* ad4 = reinterpret_cast<const float4*>(a_dst);
    float4 r0 = row[lane * 2], r1 = row[lane * 2 + 1];
    float4 a0 = as4[lane * 2], a1 = as4[lane * 2 + 1];
    float4 d0 = ad4[lane * 2], d1 = ad4[lane * 2 + 1];
    float ps = r0.x*a0.x + r0.y*a0.y + r0.z*a0.z + r0.w*a0.w
             + r1.x*a1.x + r1.y*a1.y + r1.z*a1.z + r1.w*a1.w;
    float pd = r0.x*d0.x + r0.y*d0.y + r0.z*d0.z + r0.w*d0.w
             + r1.x*d1.x + r1.y*d1.y + r1.z*d1.z + r1.w*d1.w;
    // segmented reduce within groups of 8 lanes (one head per group)
    #pragma unroll
    for (int o = 4; o; o >>= 1) {
        ps += __shfl_xor_sync(0xffffffffu, ps, o);
        pd += __shfl_xor_sync(0xffffffffu, pd, o);
    }
    float s0 = __shfl_sync(0xffffffffu, ps, 0),  s1 = __shfl_sync(0xffffffffu, ps, 8);
    float s2 = __shfl_sync(0xffffffffu, ps, 16), s3 = __shfl_sync(0xffffffffu, ps, 24);
    float d0s = __shfl_sync(0xffffffffu, pd, 0),  d1s = __shfl_sync(0xffffffffu, pd, 8);
    float d2s = __shfl_sync(0xffffffffu, pd, 16), d3s = __shfl_sync(0xffffffffu, pd, 24);
    if (lane == 0) {
        g_ssrc[warp] = make_float4(s0, s1, s2, s3);
        g_sdst[warp] = make_float4(d0s, d1s, d2s, d3s);
    }
}

// ---------------- count in-degree ----------------
__global__ void count_deg_kernel(const int* __restrict__ ei, const int* __restrict__ dst_sep) {
    int e = blockIdx.x * blockDim.x + threadIdx.x;
    if (e >= EE) return;
    int st = g_stride;
    const int* d_base = dst_sep ? dst_sep : ei + (size_t)EE * st;
    int u = d_base[(size_t)e * st];
    if (u >= 0 && u < NN) atomicAdd(&g_deg[u], 1);
}

// ---------------- multi-block exclusive scan ----------------
__global__ void scan_part1_kernel() {
    __shared__ int warpsums[32];
    int t = threadIdx.x, lane = t & 31, wid = t >> 5;
    int idx = blockIdx.x * 1024 + t;
    int v = (idx < NN) ? g_deg[idx] : 0;
    int x = v;
    #pragma unroll
    for (int o = 1; o < 32; o <<= 1) {
        int y = __shfl_up_sync(0xffffffffu, x, o);
        if (lane >= o) x += y;
    }
    if (lane == 31) warpsums[wid] = x;
    __syncthreads();
    if (wid == 0) {
        int s = warpsums[lane];
        #pragma unroll
        for (int o = 1; o < 32; o <<= 1) {
            int y = __shfl_up_sync(0xffffffffu, s, o);
            if (lane >= o) s += y;
        }
        warpsums[lane] = s;
    }
    __syncthreads();
    int incl = x + (wid > 0 ? warpsums[wid - 1] : 0);
    if (idx < NN) g_off[idx] = incl - v;       // exclusive within block
    if (t == 1023) g_bsum[blockIdx.x] = incl;  // block total (last thread's inclusive)
}

__global__ void scan_part2_kernel() {
    __shared__ int ws[2];
    int t = threadIdx.x, lane = t & 31, wid = t >> 5;   // 64 threads, 2 warps
    int v = (t < SCAN_NB) ? g_bsum[t] : 0;
    int x = v;
    #pragma unroll
    for (int o = 1; o < 32; o <<= 1) {
        int y = __shfl_up_sync(0xffffffffu, x, o);
        if (lane >= o) x += y;
    }
    if (lane == 31) ws[wid] = x;
    __syncthreads();
    int excl = x - v + (wid > 0 ? ws[0] : 0);
    if (t < SCAN_NB) g_boff[t] = excl;
}

__global__ void scan_part3_kernel() {
    int idx = blockIdx.x * blockDim.x + threadIdx.x;
    if (idx < NN) {
        int o = g_off[idx] + g_boff[idx >> 10];
        g_off[idx] = o;
        g_cursor[idx] = o;
    }
}

// ---------------- pure CSR scatter ----------------
__global__ void scatter_kernel(const int* __restrict__ ei, const int* __restrict__ dst_sep) {
    int e = blockIdx.x * blockDim.x + threadIdx.x;
    if (e >= EE) return;
    int st = g_stride;
    const int* d_base = dst_sep ? dst_sep : ei + (size_t)EE * st;
    int ud = d_base[(size_t)e * st];
    if (ud < 0 || ud >= NN) return;
    int us = ei[(size_t)e * st];
    if (us < 0) us = 0;
    if (us >= NN) us = NN - 1;
    int p = atomicAdd(&g_cursor[ud], 1);
    if (p >= 0 && p < EE) g_csr[p] = us;
}

// ---------------- fused softmax + aggregation, shuffle-shared exp weights ----------------
// blockDim (64,4). Node = 2 warps. Per 8-edge tile: lanes 0-15 compute exps for
// (edge 0-7) x (2 heads of this warp); consumers fetch via shfl. 4 exps/edge/node.
__global__ __launch_bounds__(256)
void aggregate_fused_kernel(float* __restrict__ out) {
    int t = threadIdx.x;                 // 0..63: float4 chunk
    int yn = threadIdx.y;
    int node = blockIdx.x * 4 + yn;
    if (node >= NN) return;
    int start = g_off[node], dn = g_deg[node];
    int lane = t & 31;
    int headBase = (t >> 5) * 2;         // warp 0: heads 0,1; warp 1: heads 2,3
    int hloc = (lane >> 4) & 1;          // my chunk's head within warp

    // producer role (lanes 0..15): edge slot pe, head ph
    int pe = lane & 7;
    int ph = headBase + ((lane >> 3) & 1);
    float psd = (&g_sdst[node].x)[ph];

    float4 acc = make_float4(0.f, 0.f, 0.f, 0.f);
    float z = 0.f;

    for (int i0 = 0; i0 < dn; i0 += 8) {
        int cnt = min(8, dn - i0);
        float w = 0.f; int s = 0;
        if (lane < 16 && pe < cnt) {
            s = g_csr[start + i0 + pe];
            float x = (&g_ssrc[s].x)[ph] + psd;
            x = fmaxf(x, 0.2f * x);
            w = __expf(x);
        }
        #pragma unroll
        for (int e = 0; e < 8; e++) {
            if (e >= cnt) break;                                  // cnt uniform per warp
            int   se = __shfl_sync(0xffffffffu, s, e);            // lanes 0-7 hold s
            float we = __shfl_sync(0xffffffffu, w, (hloc << 3) | e);
            float4 v = *reinterpret_cast<const float4*>(g_hp + (size_t)se * OUTF + t * 4);
            z += we;
            acc.x += we * v.x; acc.y += we * v.y;
            acc.z += we * v.z; acc.w += we * v.w;
        }
    }
    float inv = 1.f / (z + 1e-16f);
    acc.x *= inv; acc.y *= inv; acc.z *= inv; acc.w *= inv;
    *reinterpret_cast<float4*>(out + (size_t)node * OUTF + t * 4) = acc;
}

// ---------------- launch ----------------
extern "C" void kernel_launch(void* const* d_in, const int* in_sizes, int n_in,
                              void* d_out, int out_size) {
    const float* h     = nullptr;
    const int*   ei    = nullptr;
    const int*   src2  = nullptr;
    const int*   dst2  = nullptr;
    const float* W     = nullptr;
    const float* a_src = nullptr;
    const float* a_dst = nullptr;

    for (int i = 0; i < n_in; i++) {
        long sz = in_sizes[i];
        if (sz == 12800000L)      h = (const float*)d_in[i];
        else if (sz == 65536L)    W = (const float*)d_in[i];
        else if (sz == 256L) {
            if (!a_src) a_src = (const float*)d_in[i];
            else        a_dst = (const float*)d_in[i];
        }
        else if (sz == 1600000L)  ei = (const int*)d_in[i];
        else if (sz == 800000L) {
            if (!src2) src2 = (const int*)d_in[i];
            else       dst2 = (const int*)d_in[i];
        }
    }
    if (!h)                       h     = (const float*)d_in[0];
    if (!ei && !src2 && n_in > 1) ei    = (const int*)d_in[1];
    if (!W && n_in > 2)           W     = (const float*)d_in[2];
    if (!a_src && n_in > 3)       a_src = (const float*)d_in[3];
    if (!a_dst && n_in > 4)       a_dst = (const float*)d_in[4];

    const int* ebase = ei ? ei : src2;
    const int* dsep  = ei ? nullptr : dst2;
    float* out = (float*)d_out;

    cudaStream_t s2 = 0;
    cudaEvent_t ev_fork = nullptr, ev_join = nullptr;
    bool forked = (cudaStreamCreateWithFlags(&s2, cudaStreamNonBlocking) == cudaSuccess) &&
                  (cudaEventCreateWithFlags(&ev_fork, cudaEventDisableTiming) == cudaSuccess) &&
                  (cudaEventCreateWithFlags(&ev_join, cudaEventDisableTiming) == cudaSuccess);

    detect_kernel<<<1, 32>>>(ebase);

    if (forked) {
        cudaEventRecord(ev_fork, 0);
        cudaStreamWaitEvent(s2, ev_fork, 0);
    }
    cudaStream_t sb = forked ? s2 : 0;

    // CSR chain on side stream (hidden under GEMM chain)
    zero_deg_kernel<<<(NN + 255) / 256, 256, 0, sb>>>();
    count_deg_kernel<<<(EE + 255) / 256, 256, 0, sb>>>(ebase, dsep);
    scan_part1_kernel<<<SCAN_NB, 1024, 0, sb>>>();
    scan_part2_kernel<<<1, 64, 0, sb>>>();
    scan_part3_kernel<<<(NN + 255) / 256, 256, 0, sb>>>();
    scatter_kernel<<<(EE + 255) / 256, 256, 0, sb>>>(ebase, dsep);

    // GEMM chain on main stream
    dim3 tblock(32, 8);
    transpose_w_kernel<<<dim3(8, 8), tblock>>>(W);
    dim3 ggrid(OUTF / GBN, (NN + GBM - 1) / GBM);
    tf32_gemm_kernel<<<ggrid, 256>>>(h, NN);
    node_dots_kernel<<<(NN * 32 + 255) / 256, 256>>>(a_src, a_dst);

    if (forked) {
        cudaEventRecord(ev_join, s2);
        cudaStreamWaitEvent(0, ev_join, 0);
    }

    dim3 ablock(64, 4);
    aggregate_fused_kernel<<<(NN + 3) / 4, ablock>>>(out);
}

// round 10
// speedup vs baseline: 2.5529x; 1.0736x over previous
#include <cuda_runtime.h>
#include <cuda_fp16.h>
#include <cstdint>

// ---------------- Problem constants ----------------
#define NN 50000
#define EE 800000
#define KIN 256
#define HD 4
#define DD 64
#define OUTF (HD*DD)   // 256
#define SCAN_NB ((NN + 1023) / 1024)   // 49

// ---------------- Scratch (device globals; referenced ONLY from device code) ----------------
__device__ float  g_hp[(size_t)NN * OUTF];     // fp32 projected features (node_dots)
__device__ __half g_hph[(size_t)NN * OUTF];    // fp16 copy (aggregation gather)
__device__ float  g_wt[KIN * OUTF];
__device__ float4 g_ssrc[NN];
__device__ float4 g_sdst[NN];
__device__ int    g_deg[NN];
__device__ int    g_off[NN];
__device__ int    g_cursor[NN];
__device__ int    g_csr[EE];
__device__ int    g_bsum[SCAN_NB];
__device__ int    g_boff[SCAN_NB];
__device__ int    g_stride;

// ---------------- detect int64 vs int32 edge_index ----------------
__global__ void detect_kernel(const int* __restrict__ ei) {
    if (blockIdx.x == 0 && threadIdx.x == 0) {
        int odd_nz = 0, even_nz = 0;
        for (int i = 0; i < 512; i++) {
            if (ei[2 * i + 1] != 0) odd_nz++;
            if (ei[2 * i] != 0)     even_nz++;
        }
        g_stride = (odd_nz == 0 && even_nz > 0) ? 2 : 1;
    }
}

// ---------------- zero degree ----------------
__global__ void zero_deg_kernel() {
    int i = blockIdx.x * blockDim.x + threadIdx.x;
    if (i < NN) g_deg[i] = 0;
}

__device__ __forceinline__ float tf32r(float f) {
    uint32_t u;
    asm("cvt.rna.tf32.f32 %0, %1;" : "=r"(u) : "f"(f));
    return __uint_as_float(u);
}

// ---------------- transpose W (+ tf32 pre-round) ----------------
__global__ void transpose_w_kernel(const float* __restrict__ W) {
    __shared__ float tile[32][33];
    int bx = blockIdx.x * 32, by = blockIdx.y * 32;
    int tx = threadIdx.x, ty = threadIdx.y;
    #pragma unroll
    for (int r = 0; r < 4; r++)
        tile[ty + r * 8][tx] = W[(size_t)(by + ty + r * 8) * OUTF + bx + tx];
    __syncthreads();
    #pragma unroll
    for (int r = 0; r < 4; r++)
        g_wt[(size_t)(bx + ty + r * 8) * KIN + by + tx] = tf32r(tile[tx][ty + r * 8]);
}

// ---------------- tf32 tensor-core GEMM (epilogue writes fp32 + fp16) ----------------
#define GBM 128
#define GBN 128
#define GBK 32
#define LDK 36

__device__ __forceinline__ void mma_tf32(float4& d,
                                         uint32_t a0, uint32_t a1, uint32_t a2, uint32_t a3,
                                         uint32_t b0, uint32_t b1) {
    asm volatile(
        "mma.sync.aligned.m16n8k8.row.col.f32.tf32.tf32.f32 "
        "{%0,%1,%2,%3}, {%4,%5,%6,%7}, {%8,%9}, {%0,%1,%2,%3};"
        : "+f"(d.x), "+f"(d.y), "+f"(d.z), "+f"(d.w)
        : "r"(a0), "r"(a1), "r"(a2), "r"(a3), "r"(b0), "r"(b1));
}

__global__ __launch_bounds__(256, 2)
void tf32_gemm_kernel(const float* __restrict__ A, int M) {
    __shared__ uint32_t As[GBM * LDK];
    __shared__ uint32_t Bs[GBN * LDK];
    int tid  = threadIdx.x;
    int warp = tid >> 5, lane = tid & 31;
    int wm = warp & 1, wn = warp >> 1;
    int rowBase = blockIdx.y * GBM;
    int colBase = blockIdx.x * GBN;

    float4 acc[4][4];
    #pragma unroll
    for (int i = 0; i < 4; i++)
        #pragma unroll
        for (int j = 0; j < 4; j++) acc[i][j] = make_float4(0.f, 0.f, 0.f, 0.f);

    int la_row = tid >> 3;
    int la_col = (tid & 7) * 4;

    float4 pa[4], pb[4];
    #pragma unroll
    for (int r = 0; r < 4; r++) {
        int gr = rowBase + la_row + r * 32;
        pa[r] = (gr < M) ? *reinterpret_cast<const float4*>(A + (size_t)gr * KIN + la_col)
                         : make_float4(0.f, 0.f, 0.f, 0.f);
        int gn = colBase + la_row + r * 32;
        pb[r] = *reinterpret_cast<const float4*>(g_wt + (size_t)gn * KIN + la_col);
    }

    for (int k0 = 0; k0 < KIN; k0 += GBK) {
        #pragma unroll
        for (int r = 0; r < 4; r++) {
            uint4 av;
            av.x = __float_as_uint(tf32r(pa[r].x));
            av.y = __float_as_uint(tf32r(pa[r].y));
            av.z = __float_as_uint(tf32r(pa[r].z));
            av.w = __float_as_uint(tf32r(pa[r].w));
            *reinterpret_cast<uint4*>(&As[(la_row + r * 32) * LDK + la_col]) = av;
            *reinterpret_cast<uint4*>(&Bs[(la_row + r * 32) * LDK + la_col]) =
                *reinterpret_cast<uint4*>(&pb[r]);
        }
        __syncthreads();
        if (k0 + GBK < KIN) {
            #pragma unroll
            for (int r = 0; r < 4; r++) {
                int gr = rowBase + la_row + r * 32;
                pa[r] = (gr < M) ? *reinterpret_cast<const float4*>(A + (size_t)gr * KIN + k0 + GBK + la_col)
                                 : make_float4(0.f, 0.f, 0.f, 0.f);
                int gn = colBase + la_row + r * 32;
                pb[r] = *reinterpret_cast<const float4*>(g_wt + (size_t)gn * KIN + k0 + GBK + la_col);
            }
        }
        int g4 = lane >> 2, l4 = lane & 3;
        #pragma unroll
        for (int ks = 0; ks < 4; ks++) {
            int kb = ks * 8;
            uint32_t af[4][4], bf[4][2];
            #pragma unroll
            for (int mt = 0; mt < 4; mt++) {
                int r0 = wm * 64 + mt * 16 + g4;
                af[mt][0] = As[ r0      * LDK + kb + l4    ];
                af[mt][1] = As[(r0 + 8) * LDK + kb + l4    ];
                af[mt][2] = As[ r0      * LDK + kb + l4 + 4];
                af[mt][3] = As[(r0 + 8) * LDK + kb + l4 + 4];
            }
            #pragma unroll
            for (int nt = 0; nt < 4; nt++) {
                int n0 = wn * 32 + nt * 8 + g4;
                bf[nt][0] = Bs[n0 * LDK + kb + l4    ];
                bf[nt][1] = Bs[n0 * LDK + kb + l4 + 4];
            }
            #pragma unroll
            for (int mt = 0; mt < 4; mt++)
                #pragma unroll
                for (int nt = 0; nt < 4; nt++)
                    mma_tf32(acc[mt][nt], af[mt][0], af[mt][1], af[mt][2], af[mt][3],
                             bf[nt][0], bf[nt][1]);
        }
        __syncthreads();
    }

    int g4 = lane >> 2, l4 = lane & 3;
    #pragma unroll
    for (int mt = 0; mt < 4; mt++) {
        int r = rowBase + wm * 64 + mt * 16 + g4;
        #pragma unroll
        for (int nt = 0; nt < 4; nt++) {
            int c = colBase + wn * 32 + nt * 8 + l4 * 2;
            if (r < M) {
                *reinterpret_cast<float2*>(g_hp + (size_t)r * OUTF + c) =
                    make_float2(acc[mt][nt].x, acc[mt][nt].y);
                *reinterpret_cast<__half2*>(g_hph + (size_t)r * OUTF + c) =
                    __floats2half2_rn(acc[mt][nt].x, acc[mt][nt].y);
            }
            if (r + 8 < M) {
                *reinterpret_cast<float2*>(g_hp + (size_t)(r + 8) * OUTF + c) =
                    make_float2(acc[mt][nt].z, acc[mt][nt].w);
                *reinterpret_cast<__half2*>(g_hph + (size_t)(r + 8) * OUTF + c) =
                    __floats2half2_rn(acc[mt][nt].z, acc[mt][nt].w);
            }
        }
    }
}

// ---------------- per-node logits (float4 loads + segmented reduce) ----------------
__global__ void node_dots_kernel(const float* __restrict__ a_src,
                                 const float* __restrict__ a_dst) {
    int warp = (blockIdx.x * blockDim.x + threadIdx.x) >> 5;
    int lane = threadIdx.x & 31;
    if (warp >= NN) return;
    const float4* row = reinterpret_cast<const float4*>(g_hp + (size_t)warp * OUTF);
    const float4* as4 = reinterpret_cast<const float4*>(a_src);
    const float4* ad4 = reinterpret_cast<const float4*>(a_dst);
    float4 r0 = row[lane * 2], r1 = row[lane * 2 + 1];
    float4 a0 = as4[lane * 2], a1 = as4[lane * 2 + 1];
    float4 d0 = ad4[lane * 2], d1 = ad4[lane * 2 + 1];
    float ps = r0.x*a0.x + r0.y*a0.y + r0.z*a0.z + r0.w*a0.w
             + r1.x*a1.x + r1.y*a1.y + r1.z*a1.z + r1.w*a1.w;
    float pd = r0.x*d0.x + r0.y*d0.y + r0.z*d0.z + r0.w*d0.w
             + r1.x*d1.x + r1.y*d1.y + r1.z*d1.z + r1.w*d1.w;
    #pragma unroll
    for (int o = 4; o; o >>= 1) {
        ps += __shfl_xor_sync(0xffffffffu, ps, o);
        pd += __shfl_xor_sync(0xffffffffu, pd, o);
    }
    float s0 = __shfl_sync(0xffffffffu, ps, 0),  s1 = __shfl_sync(0xffffffffu, ps, 8);
    float s2 = __shfl_sync(0xffffffffu, ps, 16), s3 = __shfl_sync(0xffffffffu, ps, 24);
    float d0s = __shfl_sync(0xffffffffu, pd, 0),  d1s = __shfl_sync(0xffffffffu, pd, 8);
    float d2s = __shfl_sync(0xffffffffu, pd, 16), d3s = __shfl_sync(0xffffffffu, pd, 24);
    if (lane == 0) {
        g_ssrc[warp] = make_float4(s0, s1, s2, s3);
        g_sdst[warp] = make_float4(d0s, d1s, d2s, d3s);
    }
}

// ---------------- count in-degree ----------------
__global__ void count_deg_kernel(const int* __restrict__ ei, const int* __restrict__ dst_sep) {
    int e = blockIdx.x * blockDim.x + threadIdx.x;
    if (e >= EE) return;
    int st = g_stride;
    const int* d_base = dst_sep ? dst_sep : ei + (size_t)EE * st;
    int u = d_base[(size_t)e * st];
    if (u >= 0 && u < NN) atomicAdd(&g_deg[u], 1);
}

// ---------------- multi-block exclusive scan ----------------
__global__ void scan_part1_kernel() {
    __shared__ int warpsums[32];
    int t = threadIdx.x, lane = t & 31, wid = t >> 5;
    int idx = blockIdx.x * 1024 + t;
    int v = (idx < NN) ? g_deg[idx] : 0;
    int x = v;
    #pragma unroll
    for (int o = 1; o < 32; o <<= 1) {
        int y = __shfl_up_sync(0xffffffffu, x, o);
        if (lane >= o) x += y;
    }
    if (lane == 31) warpsums[wid] = x;
    __syncthreads();
    if (wid == 0) {
        int s = warpsums[lane];
        #pragma unroll
        for (int o = 1; o < 32; o <<= 1) {
            int y = __shfl_up_sync(0xffffffffu, s, o);
            if (lane >= o) s += y;
        }
        warpsums[lane] = s;
    }
    __syncthreads();
    int incl = x + (wid > 0 ? warpsums[wid - 1] : 0);
    if (idx < NN) g_off[idx] = incl - v;
    if (t == 1023) g_bsum[blockIdx.x] = incl;
}

__global__ void scan_part2_kernel() {
    __shared__ int ws[2];
    int t = threadIdx.x, lane = t & 31, wid = t >> 5;
    int v = (t < SCAN_NB) ? g_bsum[t] : 0;
    int x = v;
    #pragma unroll
    for (int o = 1; o < 32; o <<= 1) {
        int y = __shfl_up_sync(0xffffffffu, x, o);
        if (lane >= o) x += y;
    }
    if (lane == 31) ws[wid] = x;
    __syncthreads();
    int excl = x - v + (wid > 0 ? ws[0] : 0);
    if (t < SCAN_NB) g_boff[t] = excl;
}

__global__ void scan_part3_kernel() {
    int idx = blockIdx.x * blockDim.x + threadIdx.x;
    if (idx < NN) {
        int o = g_off[idx] + g_boff[idx >> 10];
        g_off[idx] = o;
        g_cursor[idx] = o;
    }
}

// ---------------- pure CSR scatter ----------------
__global__ void scatter_kernel(const int* __restrict__ ei, const int* __restrict__ dst_sep) {
    int e = blockIdx.x * blockDim.x + threadIdx.x;
    if (e >= EE) return;
    int st = g_stride;
    const int* d_base = dst_sep ? dst_sep : ei + (size_t)EE * st;
    int ud = d_base[(size_t)e * st];
    if (ud < 0 || ud >= NN) return;
    int us = ei[(size_t)e * st];
    if (us < 0) us = 0;
    if (us >= NN) us = NN - 1;
    int p = atomicAdd(&g_cursor[ud], 1);
    if (p >= 0 && p < EE) g_csr[p] = us;
}

// ---------------- fused softmax + aggregation: warp per node, fp16 gather ----------------
// blockDim (32,8). Lane owns 8 halfs (16B) of the node's 256-wide row; head = lane>>3.
// Per 8-edge tile all 32 lanes produce exps (edge = lane&7, head = lane>>3).
__global__ __launch_bounds__(256)
void aggregate_fused_kernel(float* __restrict__ out) {
    int lane = threadIdx.x;
    int yn = threadIdx.y;
    int node = blockIdx.x * 8 + yn;
    if (node >= NN) return;
    int start = g_off[node], dn = g_deg[node];
    int hq = lane >> 3;                  // my head (both producer and consumer role)
    int pe = lane & 7;                   // producer edge slot
    float sdv = (&g_sdst[node].x)[hq];

    float accf[8] = {0.f,0.f,0.f,0.f,0.f,0.f,0.f,0.f};
    float z = 0.f;

    for (int i0 = 0; i0 < dn; i0 += 8) {
        int cnt = min(8, dn - i0);
        float w = 0.f; int s = 0;
        if (pe < cnt) {
            s = g_csr[start + i0 + pe];              // 4-way redundant, L1 broadcast
            float x = (&g_ssrc[s].x)[hq] + sdv;
            x = fmaxf(x, 0.2f * x);
            w = __expf(x);
        }
        #pragma unroll
        for (int e = 0; e < 8; e++) {
            if (e >= cnt) break;                     // cnt uniform per warp
            int   se = __shfl_sync(0xffffffffu, s, e);           // lane e holds s for edge e
            float we = __shfl_sync(0xffffffffu, w, (hq << 3) | e);
            uint4 vu = *reinterpret_cast<const uint4*>(g_hph + (size_t)se * OUTF + lane * 8);
            const __half2* vh = reinterpret_cast<const __half2*>(&vu);
            z += we;
            #pragma unroll
            for (int q = 0; q < 4; q++) {
                float2 f = __half22float2(vh[q]);
                accf[q * 2]     += we * f.x;
                accf[q * 2 + 1] += we * f.y;
            }
        }
    }
    float inv = 1.f / (z + 1e-16f);
    float4 o0 = make_float4(accf[0]*inv, accf[1]*inv, accf[2]*inv, accf[3]*inv);
    float4 o1 = make_float4(accf[4]*inv, accf[5]*inv, accf[6]*inv, accf[7]*inv);
    *reinterpret_cast<float4*>(out + (size_t)node * OUTF + lane * 8)     = o0;
    *reinterpret_cast<float4*>(out + (size_t)node * OUTF + lane * 8 + 4) = o1;
}

// ---------------- launch ----------------
extern "C" void kernel_launch(void* const* d_in, const int* in_sizes, int n_in,
                              void* d_out, int out_size) {
    const float* h     = nullptr;
    const int*   ei    = nullptr;
    const int*   src2  = nullptr;
    const int*   dst2  = nullptr;
    const float* W     = nullptr;
    const float* a_src = nullptr;
    const float* a_dst = nullptr;

    for (int i = 0; i < n_in; i++) {
        long sz = in_sizes[i];
        if (sz == 12800000L)      h = (const float*)d_in[i];
        else if (sz == 65536L)    W = (const float*)d_in[i];
        else if (sz == 256L) {
            if (!a_src) a_src = (const float*)d_in[i];
            else        a_dst = (const float*)d_in[i];
        }
        else if (sz == 1600000L)  ei = (const int*)d_in[i];
        else if (sz == 800000L) {
            if (!src2) src2 = (const int*)d_in[i];
            else       dst2 = (const int*)d_in[i];
        }
    }
    if (!h)                       h     = (const float*)d_in[0];
    if (!ei && !src2 && n_in > 1) ei    = (const int*)d_in[1];
    if (!W && n_in > 2)           W     = (const float*)d_in[2];
    if (!a_src && n_in > 3)       a_src = (const float*)d_in[3];
    if (!a_dst && n_in > 4)       a_dst = (const float*)d_in[4];

    const int* ebase = ei ? ei : src2;
    const int* dsep  = ei ? nullptr : dst2;
    float* out = (float*)d_out;

    cudaStream_t s2 = 0;
    cudaEvent_t ev_fork = nullptr, ev_join = nullptr;
    bool forked = (cudaStreamCreateWithFlags(&s2, cudaStreamNonBlocking) == cudaSuccess) &&
                  (cudaEventCreateWithFlags(&ev_fork, cudaEventDisableTiming) == cudaSuccess) &&
                  (cudaEventCreateWithFlags(&ev_join, cudaEventDisableTiming) == cudaSuccess);

    detect_kernel<<<1, 32>>>(ebase);

    if (forked) {
        cudaEventRecord(ev_fork, 0);
        cudaStreamWaitEvent(s2, ev_fork, 0);
    }
    cudaStream_t sb = forked ? s2 : 0;

    // CSR chain on side stream (hidden under GEMM chain)
    zero_deg_kernel<<<(NN + 255) / 256, 256, 0, sb>>>();
    count_deg_kernel<<<(EE + 255) / 256, 256, 0, sb>>>(ebase, dsep);
    scan_part1_kernel<<<SCAN_NB, 1024, 0, sb>>>();
    scan_part2_kernel<<<1, 64, 0, sb>>>();
    scan_part3_kernel<<<(NN + 255) / 256, 256, 0, sb>>>();
    scatter_kernel<<<(EE + 255) / 256, 256, 0, sb>>>(ebase, dsep);

    // GEMM chain on main stream
    dim3 tblock(32, 8);
    transpose_w_kernel<<<dim3(8, 8), tblock>>>(W);
    dim3 ggrid(OUTF / GBN, (NN + GBM - 1) / GBM);
    tf32_gemm_kernel<<<ggrid, 256>>>(h, NN);
    node_dots_kernel<<<(NN * 32 + 255) / 256, 256>>>(a_src, a_dst);

    if (forked) {
        cudaEventRecord(ev_join, s2);
        cudaStreamWaitEvent(0, ev_join, 0);
    }

    dim3 ablock(32, 8);
    aggregate_fused_kernel<<<(NN + 7) / 8, ablock>>>(out);
}